// round 4
// baseline (speedup 1.0000x reference)
#include <cuda_runtime.h>
#include <math_constants.h>
#include <cstdint>

#define BATCH 8
#define SEQ   1024
#define DMODEL 768
#define NH    12
#define HDIM  64
#define IMG   32   // sqrt(SEQ)

// ---------------- scratch (device globals: no allocation allowed) ----------
__device__ float g_Q[BATCH*NH*SEQ*HDIM];
__device__ float g_K[BATCH*NH*SEQ*HDIM];
__device__ float g_V[BATCH*NH*SEQ*HDIM];
__device__ float g_X[BATCH*SEQ*DMODEL];

// ---------------- helpers --------------------------------------------------
__device__ __forceinline__ unsigned f2tf(float f) {
    unsigned r; asm("cvt.rna.tf32.f32 %0, %1;" : "=r"(r) : "f"(f)); return r;
}

__device__ __forceinline__ void mma_tf32(float* d, const unsigned* a, const unsigned* b) {
    asm volatile("mma.sync.aligned.m16n8k8.row.col.f32.tf32.tf32.f32 "
        "{%0,%1,%2,%3},{%4,%5,%6,%7},{%8,%9},{%0,%1,%2,%3};"
        : "+f"(d[0]), "+f"(d[1]), "+f"(d[2]), "+f"(d[3])
        : "r"(a[0]), "r"(a[1]), "r"(a[2]), "r"(a[3]),
          "r"(b[0]), "r"(b[1]));
}

// ---------------- TF32 GEMM: C[M,N] = A[M,K] @ W[K,N] + bias, tiles 64x64x32
// mode 0/1/2: write g_Q/g_K/g_V in head-major [B,H,S,HD]; mode 3: A=g_X, write outPlain [M,N]
__global__ void __launch_bounds__(128) gemm_tf32(
    const float* __restrict__ A_, const float* __restrict__ W,
    const float* __restrict__ bias, float* __restrict__ outPlain,
    float scale, int mode)
{
    const int N = DMODEL, K = DMODEL;
    __shared__ unsigned As[64][40];   // 64 x 32 tile, pad 40
    __shared__ unsigned Bs[32][72];   // 32 x 64 tile, pad 72

    const float* A = (mode == 3) ? (const float*)g_X : A_;

    int m0 = blockIdx.x * 64, n0 = blockIdx.y * 64;
    int tid  = threadIdx.x;
    int lane = tid & 31, warp = tid >> 5;
    int g = lane >> 2, t4 = lane & 3;
    int wm = (warp >> 1) * 32, wn = (warp & 1) * 32;

    float acc[2][4][4];
    #pragma unroll
    for (int i = 0; i < 2; i++)
        #pragma unroll
        for (int j = 0; j < 4; j++)
            #pragma unroll
            for (int r = 0; r < 4; r++) acc[i][j][r] = 0.f;

    for (int k0 = 0; k0 < K; k0 += 32) {
        #pragma unroll
        for (int j = 0; j < 4; j++) {
            int idx = tid + j * 128;
            int row = idx >> 3, c4 = (idx & 7) << 2;
            float4 v = *(const float4*)(A + (size_t)(m0 + row) * K + k0 + c4);
            As[row][c4 + 0] = f2tf(v.x); As[row][c4 + 1] = f2tf(v.y);
            As[row][c4 + 2] = f2tf(v.z); As[row][c4 + 3] = f2tf(v.w);
        }
        #pragma unroll
        for (int j = 0; j < 4; j++) {
            int idx = tid + j * 128;
            int row = idx >> 4, c4 = (idx & 15) << 2;
            float4 v = *(const float4*)(W + (size_t)(k0 + row) * N + n0 + c4);
            Bs[row][c4 + 0] = f2tf(v.x); Bs[row][c4 + 1] = f2tf(v.y);
            Bs[row][c4 + 2] = f2tf(v.z); Bs[row][c4 + 3] = f2tf(v.w);
        }
        __syncthreads();

        #pragma unroll
        for (int ks = 0; ks < 4; ks++) {
            unsigned a[2][4], b[4][2];
            #pragma unroll
            for (int mf = 0; mf < 2; mf++) {
                a[mf][0] = As[wm + mf*16 + g    ][ks*8 + t4    ];
                a[mf][1] = As[wm + mf*16 + g + 8][ks*8 + t4    ];
                a[mf][2] = As[wm + mf*16 + g    ][ks*8 + t4 + 4];
                a[mf][3] = As[wm + mf*16 + g + 8][ks*8 + t4 + 4];
            }
            #pragma unroll
            for (int nf = 0; nf < 4; nf++) {
                b[nf][0] = Bs[ks*8 + t4    ][wn + nf*8 + g];
                b[nf][1] = Bs[ks*8 + t4 + 4][wn + nf*8 + g];
            }
            #pragma unroll
            for (int mf = 0; mf < 2; mf++)
                #pragma unroll
                for (int nf = 0; nf < 4; nf++)
                    mma_tf32(acc[mf][nf], a[mf], b[nf]);
        }
        __syncthreads();
    }

    float* outH = (mode == 0) ? g_Q : (mode == 1) ? g_K : (mode == 2) ? g_V : outPlain;
    #pragma unroll
    for (int mf = 0; mf < 2; mf++) {
        #pragma unroll
        for (int nf = 0; nf < 4; nf++) {
            #pragma unroll
            for (int r = 0; r < 4; r++) {
                int m = m0 + wm + mf*16 + g + ((r >= 2) ? 8 : 0);
                int n = n0 + wn + nf*8 + t4*2 + (r & 1);
                float v = (acc[mf][nf][r] + bias[n]) * scale;
                if (mode < 3) {
                    int b_ = m >> 10, s_ = m & 1023, h_ = n >> 6, hd = n & 63;
                    outH[(((size_t)(b_ * NH + h_)) * SEQ + s_) * HDIM + hd] = v;
                } else {
                    outH[(size_t)m * N + n] = v;
                }
            }
        }
    }
}

// ---------------- flash attention with analytic relative-position bias -----
// grid: (SEQ/64, BATCH*NH), 128 threads. Each warp owns 16 q rows.
// Ps (P restage) aliases Ks: after the QK^T MMAs + a barrier, Ks is dead
// for the chunk, so its 18 KB is reused. Keeps static smem at 36 KB (<48 KB).
__global__ void __launch_bounds__(128) attn_kernel(const float* __restrict__ rel_bias)
{
    __shared__ unsigned Ks[64][72];
    __shared__ unsigned Vs[64][72];
    unsigned (*Ps)[72] = Ks;          // alias, guarded by barriers below

    int bh = blockIdx.y;
    int b_ = bh / NH, h_ = bh % NH;
    int q0 = blockIdx.x * 64;
    int tid = threadIdx.x, lane = tid & 31, warp = tid >> 5;
    int g = lane >> 2, t4 = lane & 3;

    const float* Qb = g_Q + (size_t)bh * SEQ * HDIM;
    const float* Kb = g_K + (size_t)bh * SEQ * HDIM;
    const float* Vb = g_V + (size_t)bh * SEQ * HDIM;
    const float* biasH = rel_bias + h_;   // stride NH over table rows

    int qi0 = q0 + warp * 16 + g;
    int qi1 = qi0 + 8;
    int qy0 = qi0 >> 5, qx0 = qi0 & 31;
    int qy1 = qi1 >> 5, qx1 = qi1 & 31;

    // Q fragments for the full K(head)=64, register-resident
    unsigned qa[8][4];
    #pragma unroll
    for (int ks = 0; ks < 8; ks++) {
        qa[ks][0] = f2tf(Qb[(size_t)qi0 * HDIM + ks*8 + t4    ]);
        qa[ks][1] = f2tf(Qb[(size_t)qi1 * HDIM + ks*8 + t4    ]);
        qa[ks][2] = f2tf(Qb[(size_t)qi0 * HDIM + ks*8 + t4 + 4]);
        qa[ks][3] = f2tf(Qb[(size_t)qi1 * HDIM + ks*8 + t4 + 4]);
    }

    float o[8][4];
    #pragma unroll
    for (int hf = 0; hf < 8; hf++)
        #pragma unroll
        for (int r = 0; r < 4; r++) o[hf][r] = 0.f;

    float mrow0 = -CUDART_INF_F, mrow1 = -CUDART_INF_F;
    float lrow0 = 0.f, lrow1 = 0.f;

    int pr0 = warp * 16 + g, pr1 = pr0 + 8;

    for (int kc = 0; kc < 16; kc++) {
        // cooperative load of K,V chunk (64 rows x 64 cols) as tf32
        #pragma unroll
        for (int j = 0; j < 8; j++) {
            int idx = tid + j * 128;
            int row = idx >> 4, c4 = (idx & 15) << 2;
            float4 kv = *(const float4*)(Kb + (size_t)(kc*64 + row) * HDIM + c4);
            Ks[row][c4 + 0] = f2tf(kv.x); Ks[row][c4 + 1] = f2tf(kv.y);
            Ks[row][c4 + 2] = f2tf(kv.z); Ks[row][c4 + 3] = f2tf(kv.w);
            float4 vv = *(const float4*)(Vb + (size_t)(kc*64 + row) * HDIM + c4);
            Vs[row][c4 + 0] = f2tf(vv.x); Vs[row][c4 + 1] = f2tf(vv.y);
            Vs[row][c4 + 2] = f2tf(vv.z); Vs[row][c4 + 3] = f2tf(vv.w);
        }
        __syncthreads();

        // scores: S[16 x 64] = Q @ K^T
        float s[8][4];
        #pragma unroll
        for (int nf = 0; nf < 8; nf++)
            #pragma unroll
            for (int r = 0; r < 4; r++) s[nf][r] = 0.f;

        #pragma unroll
        for (int ks = 0; ks < 8; ks++) {
            #pragma unroll
            for (int nf = 0; nf < 8; nf++) {
                unsigned bb[2] = { Ks[nf*8 + g][ks*8 + t4], Ks[nf*8 + g][ks*8 + t4 + 4] };
                mma_tf32(s[nf], qa[ks], bb);
            }
        }
        __syncthreads();   // all warps done reading Ks; its smem becomes Ps

        // analytic relative-position bias + online softmax
        float mn0 = mrow0, mn1 = mrow1;
        #pragma unroll
        for (int nf = 0; nf < 8; nf++) {
            int colbase = kc*64 + nf*8 + t4*2;
            #pragma unroll
            for (int r = 0; r < 4; r++) {
                int col = colbase + (r & 1);
                int ky = col >> 5, kx = col & 31;
                int qy = (r < 2) ? qy0 : qy1;
                int qx = (r < 2) ? qx0 : qx1;
                int ridx = (qy - ky + (IMG - 1)) * (2*IMG - 1) + (qx - kx + (IMG - 1));
                s[nf][r] += __ldg(biasH + ridx * NH);
                if (r < 2) mn0 = fmaxf(mn0, s[nf][r]); else mn1 = fmaxf(mn1, s[nf][r]);
            }
        }
        mn0 = fmaxf(mn0, __shfl_xor_sync(0xffffffffu, mn0, 1));
        mn0 = fmaxf(mn0, __shfl_xor_sync(0xffffffffu, mn0, 2));
        mn1 = fmaxf(mn1, __shfl_xor_sync(0xffffffffu, mn1, 1));
        mn1 = fmaxf(mn1, __shfl_xor_sync(0xffffffffu, mn1, 2));

        float alpha0 = __expf(mrow0 - mn0);
        float alpha1 = __expf(mrow1 - mn1);
        mrow0 = mn0; mrow1 = mn1;

        float rs0 = 0.f, rs1 = 0.f;
        #pragma unroll
        for (int nf = 0; nf < 8; nf++) {
            #pragma unroll
            for (int r = 0; r < 4; r++) {
                float p = __expf(s[nf][r] - ((r < 2) ? mn0 : mn1));
                s[nf][r] = p;
                if (r < 2) rs0 += p; else rs1 += p;
            }
        }
        rs0 += __shfl_xor_sync(0xffffffffu, rs0, 1);
        rs0 += __shfl_xor_sync(0xffffffffu, rs0, 2);
        rs1 += __shfl_xor_sync(0xffffffffu, rs1, 1);
        rs1 += __shfl_xor_sync(0xffffffffu, rs1, 2);
        lrow0 = lrow0 * alpha0 + rs0;
        lrow1 = lrow1 * alpha1 + rs1;

        #pragma unroll
        for (int hf = 0; hf < 8; hf++) {
            o[hf][0] *= alpha0; o[hf][1] *= alpha0;
            o[hf][2] *= alpha1; o[hf][3] *= alpha1;
        }

        // stage P as tf32 (c-layout -> a-layout restage; per-warp rows only)
        #pragma unroll
        for (int nf = 0; nf < 8; nf++) {
            Ps[pr0][nf*8 + t4*2    ] = f2tf(s[nf][0]);
            Ps[pr0][nf*8 + t4*2 + 1] = f2tf(s[nf][1]);
            Ps[pr1][nf*8 + t4*2    ] = f2tf(s[nf][2]);
            Ps[pr1][nf*8 + t4*2 + 1] = f2tf(s[nf][3]);
        }
        __syncwarp();

        // O += P @ V
        #pragma unroll
        for (int ks = 0; ks < 8; ks++) {
            unsigned pa[4] = { Ps[pr0][ks*8 + t4], Ps[pr1][ks*8 + t4],
                               Ps[pr0][ks*8 + t4 + 4], Ps[pr1][ks*8 + t4 + 4] };
            #pragma unroll
            for (int hf = 0; hf < 8; hf++) {
                unsigned vb[2] = { Vs[ks*8 + t4][hf*8 + g], Vs[ks*8 + t4 + 4][hf*8 + g] };
                mma_tf32(o[hf], pa, vb);
            }
        }
        __syncthreads();   // all warps done with Ps/Vs before next chunk load
    }

    float inv0 = 1.f / lrow0, inv1 = 1.f / lrow1;
    #pragma unroll
    for (int hf = 0; hf < 8; hf++) {
        int hd = hf*8 + t4*2;
        size_t base0 = ((size_t)b_ * SEQ + qi0) * DMODEL + h_ * HDIM + hd;
        size_t base1 = ((size_t)b_ * SEQ + qi1) * DMODEL + h_ * HDIM + hd;
        g_X[base0    ] = o[hf][0] * inv0;
        g_X[base0 + 1] = o[hf][1] * inv0;
        g_X[base1    ] = o[hf][2] * inv1;
        g_X[base1 + 1] = o[hf][3] * inv1;
    }
}

// ---------------- launcher -------------------------------------------------
extern "C" void kernel_launch(void* const* d_in, const int* in_sizes, int n_in,
                              void* d_out, int out_size) {
    const float* inputs_q  = (const float*)d_in[0];
    const float* inputs_kv = (const float*)d_in[1];
    const float* Wq = (const float*)d_in[2];
    const float* bq = (const float*)d_in[3];
    const float* Wk = (const float*)d_in[4];
    const float* bk = (const float*)d_in[5];
    const float* Wv = (const float*)d_in[6];
    const float* bv = (const float*)d_in[7];
    const float* Wo = (const float*)d_in[8];
    const float* bo = (const float*)d_in[9];
    const float* rel_bias = (const float*)d_in[10];
    // d_in[11] = pos : unused (index computed analytically in-kernel)
    float* out = (float*)d_out;

    dim3 gg(BATCH * SEQ / 64, DMODEL / 64);   // 128 x 12
    gemm_tf32<<<gg, 128>>>(inputs_q,  Wq, bq, nullptr, 0.125f, 0);
    gemm_tf32<<<gg, 128>>>(inputs_kv, Wk, bk, nullptr, 1.0f,   1);
    gemm_tf32<<<gg, 128>>>(inputs_kv, Wv, bv, nullptr, 1.0f,   2);

    dim3 ga(SEQ / 64, BATCH * NH);            // 16 x 96
    attn_kernel<<<ga, 128>>>(rel_bias);

    gemm_tf32<<<gg, 128>>>(nullptr, Wo, bo, out, 1.0f, 3);
}

// round 5
// speedup vs baseline: 1.1506x; 1.1506x over previous
#include <cuda_runtime.h>
#include <math_constants.h>
#include <cstdint>

#define BATCH 8
#define SEQ   1024
#define DMODEL 768
#define NH    12
#define HDIM  64
#define IMG   32            // sqrt(SEQ)
#define TABLE 3969          // (2*IMG-1)^2

// ---------------- scratch (device globals: no allocation allowed) ----------
__device__ float g_Q[BATCH*NH*SEQ*HDIM];
__device__ float g_K[BATCH*NH*SEQ*HDIM];
__device__ float g_V[BATCH*NH*SEQ*HDIM];
__device__ float g_X[BATCH*SEQ*DMODEL];
__device__ float g_biasT[NH*TABLE];      // rel_bias transposed: [H][TABLE]

// ---------------- helpers --------------------------------------------------
__device__ __forceinline__ unsigned f2tf(float f) {
    unsigned r; asm("cvt.rna.tf32.f32 %0, %1;" : "=r"(r) : "f"(f)); return r;
}

__device__ __forceinline__ void mma_tf32(float* d, const unsigned* a, const unsigned* b) {
    asm volatile("mma.sync.aligned.m16n8k8.row.col.f32.tf32.tf32.f32 "
        "{%0,%1,%2,%3},{%4,%5,%6,%7},{%8,%9},{%0,%1,%2,%3};"
        : "+f"(d[0]), "+f"(d[1]), "+f"(d[2]), "+f"(d[3])
        : "r"(a[0]), "r"(a[1]), "r"(a[2]), "r"(a[3]),
          "r"(b[0]), "r"(b[1]));
}

// ---------------- bias transpose: [TABLE,H] -> [H,TABLE] -------------------
__global__ void transpose_bias(const float* __restrict__ rb) {
    int i = blockIdx.x * blockDim.x + threadIdx.x;
    if (i < TABLE * NH) {
        int t = i / NH, h = i % NH;
        g_biasT[h * TABLE + t] = rb[i];
    }
}

// ---------------- TF32 GEMM: C[M,N] = A[M,K] @ W[K,N] + bias ---------------
// mode 0: single, write g_Q head-major (scaled 1/8)
// mode 1: DUAL  , W1->g_K, W2->g_V head-major
// mode 3: single, A=g_X, write outPlain [M,N]
// Strides: As 36 (=4 mod 32: a-frag (g,t4) conflict-free), Bs 72 (=8 mod 32:
// b-frag (t4,g) conflict-free). All staging stores packed uint4 (16B aligned
// since strides are multiples of 4 words).
__global__ void __launch_bounds__(128) gemm_tf32(
    const float* __restrict__ A_,
    const float* __restrict__ W1, const float* __restrict__ b1,
    const float* __restrict__ W2, const float* __restrict__ b2,
    float* __restrict__ outPlain, float scale, int mode)
{
    const int N = DMODEL, K = DMODEL;
    __shared__ unsigned As[64][36];
    __shared__ unsigned Bs[2][32][72];

    const bool dual = (mode == 1);
    const float* A = (mode == 3) ? (const float*)g_X : A_;

    int m0 = blockIdx.x * 64, n0 = blockIdx.y * 64;
    int tid  = threadIdx.x;
    int lane = tid & 31, warp = tid >> 5;
    int g = lane >> 2, t4 = lane & 3;
    int wm = (warp >> 1) * 32, wn = (warp & 1) * 32;

    float acc[2][2][4][4];   // [buf][mf][nf][r]
    #pragma unroll
    for (int u = 0; u < 2; u++)
        #pragma unroll
        for (int i = 0; i < 2; i++)
            #pragma unroll
            for (int j = 0; j < 4; j++)
                #pragma unroll
                for (int r = 0; r < 4; r++) acc[u][i][j][r] = 0.f;

    for (int k0 = 0; k0 < K; k0 += 32) {
        #pragma unroll
        for (int j = 0; j < 4; j++) {
            int idx = tid + j * 128;
            int row = idx >> 3, c4 = (idx & 7) << 2;
            float4 v = *(const float4*)(A + (size_t)(m0 + row) * K + k0 + c4);
            uint4 p = { f2tf(v.x), f2tf(v.y), f2tf(v.z), f2tf(v.w) };
            *(uint4*)&As[row][c4] = p;
        }
        #pragma unroll
        for (int j = 0; j < 4; j++) {
            int idx = tid + j * 128;
            int row = idx >> 4, c4 = (idx & 15) << 2;
            float4 v = *(const float4*)(W1 + (size_t)(k0 + row) * N + n0 + c4);
            uint4 p = { f2tf(v.x), f2tf(v.y), f2tf(v.z), f2tf(v.w) };
            *(uint4*)&Bs[0][row][c4] = p;
        }
        if (dual) {
            #pragma unroll
            for (int j = 0; j < 4; j++) {
                int idx = tid + j * 128;
                int row = idx >> 4, c4 = (idx & 15) << 2;
                float4 v = *(const float4*)(W2 + (size_t)(k0 + row) * N + n0 + c4);
                uint4 p = { f2tf(v.x), f2tf(v.y), f2tf(v.z), f2tf(v.w) };
                *(uint4*)&Bs[1][row][c4] = p;
            }
        }
        __syncthreads();

        #pragma unroll
        for (int ks = 0; ks < 4; ks++) {
            unsigned a[2][4];
            #pragma unroll
            for (int mf = 0; mf < 2; mf++) {
                a[mf][0] = As[wm + mf*16 + g    ][ks*8 + t4    ];
                a[mf][1] = As[wm + mf*16 + g + 8][ks*8 + t4    ];
                a[mf][2] = As[wm + mf*16 + g    ][ks*8 + t4 + 4];
                a[mf][3] = As[wm + mf*16 + g + 8][ks*8 + t4 + 4];
            }
            #pragma unroll
            for (int nf = 0; nf < 4; nf++) {
                unsigned b0[2] = { Bs[0][ks*8 + t4][wn + nf*8 + g],
                                   Bs[0][ks*8 + t4 + 4][wn + nf*8 + g] };
                #pragma unroll
                for (int mf = 0; mf < 2; mf++)
                    mma_tf32(acc[0][mf][nf], a[mf], b0);
                if (dual) {
                    unsigned b1r[2] = { Bs[1][ks*8 + t4][wn + nf*8 + g],
                                        Bs[1][ks*8 + t4 + 4][wn + nf*8 + g] };
                    #pragma unroll
                    for (int mf = 0; mf < 2; mf++)
                        mma_tf32(acc[1][mf][nf], a[mf], b1r);
                }
            }
        }
        __syncthreads();
    }

    int nbuf = dual ? 2 : 1;
    for (int u = 0; u < nbuf; u++) {
        float* outH = (mode == 0) ? g_Q : (mode == 1) ? (u == 0 ? g_K : g_V) : outPlain;
        const float* bias = (u == 0) ? b1 : b2;
        #pragma unroll
        for (int mf = 0; mf < 2; mf++) {
            #pragma unroll
            for (int nf = 0; nf < 4; nf++) {
                #pragma unroll
                for (int rr = 0; rr < 2; rr++) {            // row pair: r={0,1} / {2,3}
                    int m = m0 + wm + mf*16 + g + (rr ? 8 : 0);
                    int n = n0 + wn + nf*8 + t4*2;          // even; n,n+1 same head
                    float2 v;
                    v.x = (acc[u][mf][nf][rr*2    ] + bias[n    ]) * scale;
                    v.y = (acc[u][mf][nf][rr*2 + 1] + bias[n + 1]) * scale;
                    if (mode < 3) {
                        int b_ = m >> 10, s_ = m & 1023, h_ = n >> 6, hd = n & 63;
                        *(float2*)&outH[(((size_t)(b_ * NH + h_)) * SEQ + s_) * HDIM + hd] = v;
                    } else {
                        *(float2*)&outH[(size_t)m * N + n] = v;
                    }
                }
            }
        }
    }
}

// ---------------- flash attention with analytic relative-position bias -----
// grid: (SEQ/64, BATCH*NH), 128 threads. Each warp owns 16 q rows.
// Strides: Ks/Ps 68 (=4 mod 32: (g,t4) frag pattern conflict-free),
//          Vs 72 (=8 mod 32: (t4,g) frag pattern conflict-free).
// Ps aliases Ks (dead after QK MMAs + barrier). Bias read from g_biasT
// ([H][TABLE]) so consecutive-dx gathers are cache-line local.
__global__ void __launch_bounds__(128) attn_kernel()
{
    __shared__ unsigned Ks[64][68];
    __shared__ unsigned Vs[64][72];
    unsigned (*Ps)[68] = Ks;          // alias, guarded by barriers below

    int bh = blockIdx.y;
    int b_ = bh / NH, h_ = bh % NH;
    int q0 = blockIdx.x * 64;
    int tid = threadIdx.x, lane = tid & 31, warp = tid >> 5;
    int g = lane >> 2, t4 = lane & 3;

    const float* Qb = g_Q + (size_t)bh * SEQ * HDIM;
    const float* Kb = g_K + (size_t)bh * SEQ * HDIM;
    const float* Vb = g_V + (size_t)bh * SEQ * HDIM;
    const float* biasHT = g_biasT + (size_t)h_ * TABLE;

    int qi0 = q0 + warp * 16 + g;
    int qi1 = qi0 + 8;
    int qy0 = qi0 >> 5, qx0 = qi0 & 31;
    int qy1 = qi1 >> 5, qx1 = qi1 & 31;

    // Q fragments for the full K(head)=64, register-resident
    unsigned qa[8][4];
    #pragma unroll
    for (int ks = 0; ks < 8; ks++) {
        qa[ks][0] = f2tf(Qb[(size_t)qi0 * HDIM + ks*8 + t4    ]);
        qa[ks][1] = f2tf(Qb[(size_t)qi1 * HDIM + ks*8 + t4    ]);
        qa[ks][2] = f2tf(Qb[(size_t)qi0 * HDIM + ks*8 + t4 + 4]);
        qa[ks][3] = f2tf(Qb[(size_t)qi1 * HDIM + ks*8 + t4 + 4]);
    }

    float o[8][4];
    #pragma unroll
    for (int hf = 0; hf < 8; hf++)
        #pragma unroll
        for (int r = 0; r < 4; r++) o[hf][r] = 0.f;

    float mrow0 = -CUDART_INF_F, mrow1 = -CUDART_INF_F;
    float lrow0 = 0.f, lrow1 = 0.f;

    int pr0 = warp * 16 + g, pr1 = pr0 + 8;

    for (int kc = 0; kc < 16; kc++) {
        // cooperative load of K,V chunk (64 rows x 64 cols) as tf32, packed STS
        #pragma unroll
        for (int j = 0; j < 8; j++) {
            int idx = tid + j * 128;
            int row = idx >> 4, c4 = (idx & 15) << 2;
            float4 kv = *(const float4*)(Kb + (size_t)(kc*64 + row) * HDIM + c4);
            uint4 kp = { f2tf(kv.x), f2tf(kv.y), f2tf(kv.z), f2tf(kv.w) };
            *(uint4*)&Ks[row][c4] = kp;
            float4 vv = *(const float4*)(Vb + (size_t)(kc*64 + row) * HDIM + c4);
            uint4 vp = { f2tf(vv.x), f2tf(vv.y), f2tf(vv.z), f2tf(vv.w) };
            *(uint4*)&Vs[row][c4] = vp;
        }
        __syncthreads();

        // scores: S[16 x 64] = Q @ K^T
        float s[8][4];
        #pragma unroll
        for (int nf = 0; nf < 8; nf++)
            #pragma unroll
            for (int r = 0; r < 4; r++) s[nf][r] = 0.f;

        #pragma unroll
        for (int ks = 0; ks < 8; ks++) {
            #pragma unroll
            for (int nf = 0; nf < 8; nf++) {
                unsigned bb[2] = { Ks[nf*8 + g][ks*8 + t4], Ks[nf*8 + g][ks*8 + t4 + 4] };
                mma_tf32(s[nf], qa[ks], bb);
            }
        }
        __syncthreads();   // all warps done reading Ks; its smem becomes Ps

        // analytic relative-position bias + online softmax
        float mn0 = mrow0, mn1 = mrow1;
        #pragma unroll
        for (int nf = 0; nf < 8; nf++) {
            int colbase = kc*64 + nf*8 + t4*2;
            #pragma unroll
            for (int r = 0; r < 4; r++) {
                int col = colbase + (r & 1);
                int ky = col >> 5, kx = col & 31;
                int qy = (r < 2) ? qy0 : qy1;
                int qx = (r < 2) ? qx0 : qx1;
                int ridx = (qy - ky + (IMG - 1)) * (2*IMG - 1) + (qx - kx + (IMG - 1));
                s[nf][r] += __ldg(biasHT + ridx);
                if (r < 2) mn0 = fmaxf(mn0, s[nf][r]); else mn1 = fmaxf(mn1, s[nf][r]);
            }
        }
        mn0 = fmaxf(mn0, __shfl_xor_sync(0xffffffffu, mn0, 1));
        mn0 = fmaxf(mn0, __shfl_xor_sync(0xffffffffu, mn0, 2));
        mn1 = fmaxf(mn1, __shfl_xor_sync(0xffffffffu, mn1, 1));
        mn1 = fmaxf(mn1, __shfl_xor_sync(0xffffffffu, mn1, 2));

        float alpha0 = __expf(mrow0 - mn0);
        float alpha1 = __expf(mrow1 - mn1);
        mrow0 = mn0; mrow1 = mn1;

        float rs0 = 0.f, rs1 = 0.f;
        #pragma unroll
        for (int nf = 0; nf < 8; nf++) {
            #pragma unroll
            for (int r = 0; r < 4; r++) {
                float p = __expf(s[nf][r] - ((r < 2) ? mn0 : mn1));
                s[nf][r] = p;
                if (r < 2) rs0 += p; else rs1 += p;
            }
        }
        rs0 += __shfl_xor_sync(0xffffffffu, rs0, 1);
        rs0 += __shfl_xor_sync(0xffffffffu, rs0, 2);
        rs1 += __shfl_xor_sync(0xffffffffu, rs1, 1);
        rs1 += __shfl_xor_sync(0xffffffffu, rs1, 2);
        lrow0 = lrow0 * alpha0 + rs0;
        lrow1 = lrow1 * alpha1 + rs1;

        #pragma unroll
        for (int hf = 0; hf < 8; hf++) {
            o[hf][0] *= alpha0; o[hf][1] *= alpha0;
            o[hf][2] *= alpha1; o[hf][3] *= alpha1;
        }

        // stage P as tf32 (c-layout -> a-layout restage; per-warp rows only)
        #pragma unroll
        for (int nf = 0; nf < 8; nf++) {
            uint2 p0 = { f2tf(s[nf][0]), f2tf(s[nf][1]) };
            uint2 p1 = { f2tf(s[nf][2]), f2tf(s[nf][3]) };
            *(uint2*)&Ps[pr0][nf*8 + t4*2] = p0;
            *(uint2*)&Ps[pr1][nf*8 + t4*2] = p1;
        }
        __syncwarp();

        // O += P @ V
        #pragma unroll
        for (int ks = 0; ks < 8; ks++) {
            unsigned pa[4] = { Ps[pr0][ks*8 + t4], Ps[pr1][ks*8 + t4],
                               Ps[pr0][ks*8 + t4 + 4], Ps[pr1][ks*8 + t4 + 4] };
            #pragma unroll
            for (int hf = 0; hf < 8; hf++) {
                unsigned vb[2] = { Vs[ks*8 + t4][hf*8 + g], Vs[ks*8 + t4 + 4][hf*8 + g] };
                mma_tf32(o[hf], pa, vb);
            }
        }
        __syncthreads();   // all warps done with Ps/Vs before next chunk load
    }

    float inv0 = 1.f / lrow0, inv1 = 1.f / lrow1;
    #pragma unroll
    for (int hf = 0; hf < 8; hf++) {
        int hd = hf*8 + t4*2;
        size_t base0 = ((size_t)b_ * SEQ + qi0) * DMODEL + h_ * HDIM + hd;
        size_t base1 = ((size_t)b_ * SEQ + qi1) * DMODEL + h_ * HDIM + hd;
        float2 w0 = { o[hf][0] * inv0, o[hf][1] * inv0 };
        float2 w1 = { o[hf][2] * inv1, o[hf][3] * inv1 };
        *(float2*)&g_X[base0] = w0;
        *(float2*)&g_X[base1] = w1;
    }
}

// ---------------- launcher -------------------------------------------------
extern "C" void kernel_launch(void* const* d_in, const int* in_sizes, int n_in,
                              void* d_out, int out_size) {
    const float* inputs_q  = (const float*)d_in[0];
    const float* inputs_kv = (const float*)d_in[1];
    const float* Wq = (const float*)d_in[2];
    const float* bq = (const float*)d_in[3];
    const float* Wk = (const float*)d_in[4];
    const float* bk = (const float*)d_in[5];
    const float* Wv = (const float*)d_in[6];
    const float* bv = (const float*)d_in[7];
    const float* Wo = (const float*)d_in[8];
    const float* bo = (const float*)d_in[9];
    const float* rel_bias = (const float*)d_in[10];
    // d_in[11] = pos : unused (index computed analytically in-kernel)
    float* out = (float*)d_out;

    transpose_bias<<<(TABLE * NH + 255) / 256, 256>>>(rel_bias);

    dim3 gg(BATCH * SEQ / 64, DMODEL / 64);   // 128 x 12
    gemm_tf32<<<gg, 128>>>(inputs_q,  Wq, bq, nullptr, nullptr, nullptr, 0.125f, 0);
    gemm_tf32<<<gg, 128>>>(inputs_kv, Wk, bk, Wv, bv, nullptr, 1.0f, 1);   // K+V fused

    dim3 ga(SEQ / 64, BATCH * NH);            // 16 x 96
    attn_kernel<<<ga, 128>>>();

    gemm_tf32<<<gg, 128>>>(nullptr, Wo, bo, nullptr, nullptr, out, 1.0f, 3);
}

// round 7
// speedup vs baseline: 1.1992x; 1.0422x over previous
#include <cuda_runtime.h>
#include <math_constants.h>
#include <cstdint>

#define BATCH 8
#define SEQ   1024
#define DMODEL 768
#define NH    12
#define HDIM  64
#define IMG   32            // sqrt(SEQ)
#define TABLE 3969          // (2*IMG-1)^2

// ---------------- scratch (device globals: no allocation allowed) ----------
__device__ float g_Q[BATCH*NH*SEQ*HDIM];
__device__ float g_K[BATCH*NH*SEQ*HDIM];
__device__ float g_V[BATCH*NH*SEQ*HDIM];
__device__ float g_X[BATCH*SEQ*DMODEL];
__device__ float g_biasT[NH*TABLE];      // rel_bias transposed: [H][TABLE]

// ---------------- helpers --------------------------------------------------
__device__ __forceinline__ unsigned f2tf(float f) {
    unsigned r; asm("cvt.rna.tf32.f32 %0, %1;" : "=r"(r) : "f"(f)); return r;
}

__device__ __forceinline__ void mma_tf32(float* d, const unsigned* a, const unsigned* b) {
    asm volatile("mma.sync.aligned.m16n8k8.row.col.f32.tf32.tf32.f32 "
        "{%0,%1,%2,%3},{%4,%5,%6,%7},{%8,%9},{%0,%1,%2,%3};"
        : "+f"(d[0]), "+f"(d[1]), "+f"(d[2]), "+f"(d[3])
        : "r"(a[0]), "r"(a[1]), "r"(a[2]), "r"(a[3]),
          "r"(b[0]), "r"(b[1]));
}

// ---------------- bias transpose: [TABLE,H] -> [H,TABLE] -------------------
__global__ void transpose_bias(const float* __restrict__ rb) {
    int i = blockIdx.x * blockDim.x + threadIdx.x;
    if (i < TABLE * NH) {
        int t = i / NH, h = i % NH;
        g_biasT[h * TABLE + t] = rb[i];
    }
}

// ---------------- TF32 GEMM, 128x64 tile, 256 thr, reg-prefetch pipeline ---
// mode 0 (QKV): grid.y = 36; y/12 selects Q/K/V (A, W, bias, scale, head-major out)
// mode 1 (out): grid.y = 12; A = g_X, plain [M,N] output.
// Strides: As 36 (=4 mod 32, a-frag (g,t4) conflict-free),
//          Bs 72 (=8 mod 32, b-frag (t4,g) conflict-free).
__global__ void __launch_bounds__(256) gemm128(
    const float* __restrict__ Aq, const float* __restrict__ Akv,
    const float* __restrict__ W0, const float* __restrict__ c0,
    const float* __restrict__ W1, const float* __restrict__ c1,
    const float* __restrict__ W2, const float* __restrict__ c2,
    float* __restrict__ outPlain, int mode)
{
    const int N = DMODEL, K = DMODEL;
    __shared__ unsigned As[128][36];
    __shared__ unsigned Bs[32][72];

    const float* A; const float* W; const float* bias;
    float* outH; float scale; int headmajor;
    int ybase;
    if (mode == 0) {
        int sel = blockIdx.y / 12; ybase = blockIdx.y % 12;
        A    = (sel == 0) ? Aq : Akv;
        W    = (sel == 0) ? W0 : (sel == 1) ? W1 : W2;
        bias = (sel == 0) ? c0 : (sel == 1) ? c1 : c2;
        outH = (sel == 0) ? g_Q : (sel == 1) ? g_K : g_V;
        scale = (sel == 0) ? 0.125f : 1.0f;
        headmajor = 1;
    } else {
        ybase = blockIdx.y;
        A = (const float*)g_X; W = W0; bias = c0;
        outH = outPlain; scale = 1.0f; headmajor = 0;
    }

    int m0 = blockIdx.x * 128, n0 = ybase * 64;
    int tid  = threadIdx.x;
    int lane = tid & 31, warp = tid >> 5;
    int g = lane >> 2, t4 = lane & 3;
    int wm = (warp >> 1) * 32, wn = (warp & 1) * 32;

    float acc[2][4][4];
    #pragma unroll
    for (int i = 0; i < 2; i++)
        #pragma unroll
        for (int j = 0; j < 4; j++)
            #pragma unroll
            for (int r = 0; r < 4; r++) acc[i][j][r] = 0.f;

    // prefetch registers
    float4 ar[4], br[2];
    // rows/cols for staging (fixed per thread)
    int aRow[4], aC4[4], bRow[2], bC4[2];
    #pragma unroll
    for (int j = 0; j < 4; j++) {
        int idx = tid + j * 256;               // 0..1023 : 128 rows x 8 float4
        aRow[j] = idx >> 3; aC4[j] = (idx & 7) << 2;
    }
    #pragma unroll
    for (int j = 0; j < 2; j++) {
        int idx = tid + j * 256;               // 0..511 : 32 rows x 16 float4
        bRow[j] = idx >> 4; bC4[j] = (idx & 15) << 2;
    }

    // initial global load (chunk 0)
    #pragma unroll
    for (int j = 0; j < 4; j++)
        ar[j] = *(const float4*)(A + (size_t)(m0 + aRow[j]) * K + aC4[j]);
    #pragma unroll
    for (int j = 0; j < 2; j++)
        br[j] = *(const float4*)(W + (size_t)bRow[j] * N + n0 + bC4[j]);

    const int NCHUNK = K / 32;                 // 24
    for (int kc = 0; kc < NCHUNK; kc++) {
        // stage current regs -> smem (tf32)
        #pragma unroll
        for (int j = 0; j < 4; j++) {
            uint4 p = { f2tf(ar[j].x), f2tf(ar[j].y), f2tf(ar[j].z), f2tf(ar[j].w) };
            *(uint4*)&As[aRow[j]][aC4[j]] = p;
        }
        #pragma unroll
        for (int j = 0; j < 2; j++) {
            uint4 p = { f2tf(br[j].x), f2tf(br[j].y), f2tf(br[j].z), f2tf(br[j].w) };
            *(uint4*)&Bs[bRow[j]][bC4[j]] = p;
        }
        __syncthreads();

        // prefetch next chunk into regs (overlaps with MMAs below)
        if (kc + 1 < NCHUNK) {
            int k0 = (kc + 1) * 32;
            #pragma unroll
            for (int j = 0; j < 4; j++)
                ar[j] = *(const float4*)(A + (size_t)(m0 + aRow[j]) * K + k0 + aC4[j]);
            #pragma unroll
            for (int j = 0; j < 2; j++)
                br[j] = *(const float4*)(W + (size_t)(k0 + bRow[j]) * N + n0 + bC4[j]);
        }

        #pragma unroll
        for (int ks = 0; ks < 4; ks++) {
            unsigned a[2][4];
            #pragma unroll
            for (int mf = 0; mf < 2; mf++) {
                a[mf][0] = As[wm + mf*16 + g    ][ks*8 + t4    ];
                a[mf][1] = As[wm + mf*16 + g + 8][ks*8 + t4    ];
                a[mf][2] = As[wm + mf*16 + g    ][ks*8 + t4 + 4];
                a[mf][3] = As[wm + mf*16 + g + 8][ks*8 + t4 + 4];
            }
            #pragma unroll
            for (int nf = 0; nf < 4; nf++) {
                unsigned b[2] = { Bs[ks*8 + t4    ][wn + nf*8 + g],
                                  Bs[ks*8 + t4 + 4][wn + nf*8 + g] };
                #pragma unroll
                for (int mf = 0; mf < 2; mf++)
                    mma_tf32(acc[mf][nf], a[mf], b);
            }
        }
        __syncthreads();
    }

    // epilogue
    #pragma unroll
    for (int mf = 0; mf < 2; mf++) {
        #pragma unroll
        for (int nf = 0; nf < 4; nf++) {
            #pragma unroll
            for (int rr = 0; rr < 2; rr++) {
                int m = m0 + wm + mf*16 + g + (rr ? 8 : 0);
                int n = n0 + wn + nf*8 + t4*2;
                float2 v;
                v.x = (acc[mf][nf][rr*2    ] + bias[n    ]) * scale;
                v.y = (acc[mf][nf][rr*2 + 1] + bias[n + 1]) * scale;
                if (headmajor) {
                    int b_ = m >> 10, s_ = m & 1023, h_ = n >> 6, hd = n & 63;
                    *(float2*)&outH[(((size_t)(b_ * NH + h_)) * SEQ + s_) * HDIM + hd] = v;
                } else {
                    *(float2*)&outH[(size_t)m * N + n] = v;
                }
            }
        }
    }
}

// ---------------- flash attention with analytic relative-position bias -----
// grid: (SEQ/64, BATCH*NH), 128 threads. Each warp owns 16 q rows.
// Strides: Ks/Ps 68 (=4 mod 32: (g,t4) frag pattern conflict-free),
//          Vs 72 (=8 mod 32: (t4,g) frag pattern conflict-free).
// Ps aliases Ks (dead after QK MMAs + barrier). Bias read from g_biasT.
__global__ void __launch_bounds__(128) attn_kernel()
{
    __shared__ unsigned Ks[64][68];
    __shared__ unsigned Vs[64][72];
    unsigned (*Ps)[68] = Ks;          // alias, guarded by barriers below

    int bh = blockIdx.y;
    int b_ = bh / NH, h_ = bh % NH;
    int q0 = blockIdx.x * 64;
    int tid = threadIdx.x, lane = tid & 31, warp = tid >> 5;
    int g = lane >> 2, t4 = lane & 3;

    const float* Qb = g_Q + (size_t)bh * SEQ * HDIM;
    const float* Kb = g_K + (size_t)bh * SEQ * HDIM;
    const float* Vb = g_V + (size_t)bh * SEQ * HDIM;
    const float* biasHT = g_biasT + (size_t)h_ * TABLE;

    int qi0 = q0 + warp * 16 + g;
    int qi1 = qi0 + 8;
    int qy0 = qi0 >> 5, qx0 = qi0 & 31;
    int qy1 = qi1 >> 5, qx1 = qi1 & 31;

    unsigned qa[8][4];
    #pragma unroll
    for (int ks = 0; ks < 8; ks++) {
        qa[ks][0] = f2tf(Qb[(size_t)qi0 * HDIM + ks*8 + t4    ]);
        qa[ks][1] = f2tf(Qb[(size_t)qi1 * HDIM + ks*8 + t4    ]);
        qa[ks][2] = f2tf(Qb[(size_t)qi0 * HDIM + ks*8 + t4 + 4]);
        qa[ks][3] = f2tf(Qb[(size_t)qi1 * HDIM + ks*8 + t4 + 4]);
    }

    float o[8][4];
    #pragma unroll
    for (int hf = 0; hf < 8; hf++)
        #pragma unroll
        for (int r = 0; r < 4; r++) o[hf][r] = 0.f;

    float mrow0 = -CUDART_INF_F, mrow1 = -CUDART_INF_F;
    float lrow0 = 0.f, lrow1 = 0.f;

    int pr0 = warp * 16 + g, pr1 = pr0 + 8;

    for (int kc = 0; kc < 16; kc++) {
        #pragma unroll
        for (int j = 0; j < 8; j++) {
            int idx = tid + j * 128;
            int row = idx >> 4, c4 = (idx & 15) << 2;
            float4 kv = *(const float4*)(Kb + (size_t)(kc*64 + row) * HDIM + c4);
            uint4 kp = { f2tf(kv.x), f2tf(kv.y), f2tf(kv.z), f2tf(kv.w) };
            *(uint4*)&Ks[row][c4] = kp;
            float4 vv = *(const float4*)(Vb + (size_t)(kc*64 + row) * HDIM + c4);
            uint4 vp = { f2tf(vv.x), f2tf(vv.y), f2tf(vv.z), f2tf(vv.w) };
            *(uint4*)&Vs[row][c4] = vp;
        }
        __syncthreads();

        float s[8][4];
        #pragma unroll
        for (int nf = 0; nf < 8; nf++)
            #pragma unroll
            for (int r = 0; r < 4; r++) s[nf][r] = 0.f;

        #pragma unroll
        for (int ks = 0; ks < 8; ks++) {
            #pragma unroll
            for (int nf = 0; nf < 8; nf++) {
                unsigned bb[2] = { Ks[nf*8 + g][ks*8 + t4], Ks[nf*8 + g][ks*8 + t4 + 4] };
                mma_tf32(s[nf], qa[ks], bb);
            }
        }
        __syncthreads();   // all warps done reading Ks; its smem becomes Ps

        float mn0 = mrow0, mn1 = mrow1;
        #pragma unroll
        for (int nf = 0; nf < 8; nf++) {
            int colbase = kc*64 + nf*8 + t4*2;
            #pragma unroll
            for (int r = 0; r < 4; r++) {
                int col = colbase + (r & 1);
                int ky = col >> 5, kx = col & 31;
                int qy = (r < 2) ? qy0 : qy1;
                int qx = (r < 2) ? qx0 : qx1;
                int ridx = (qy - ky + (IMG - 1)) * (2*IMG - 1) + (qx - kx + (IMG - 1));
                s[nf][r] += __ldg(biasHT + ridx);
                if (r < 2) mn0 = fmaxf(mn0, s[nf][r]); else mn1 = fmaxf(mn1, s[nf][r]);
            }
        }
        mn0 = fmaxf(mn0, __shfl_xor_sync(0xffffffffu, mn0, 1));
        mn0 = fmaxf(mn0, __shfl_xor_sync(0xffffffffu, mn0, 2));
        mn1 = fmaxf(mn1, __shfl_xor_sync(0xffffffffu, mn1, 1));
        mn1 = fmaxf(mn1, __shfl_xor_sync(0xffffffffu, mn1, 2));

        float alpha0 = __expf(mrow0 - mn0);
        float alpha1 = __expf(mrow1 - mn1);
        mrow0 = mn0; mrow1 = mn1;

        float rs0 = 0.f, rs1 = 0.f;
        #pragma unroll
        for (int nf = 0; nf < 8; nf++) {
            #pragma unroll
            for (int r = 0; r < 4; r++) {
                float p = __expf(s[nf][r] - ((r < 2) ? mn0 : mn1));
                s[nf][r] = p;
                if (r < 2) rs0 += p; else rs1 += p;
            }
        }
        rs0 += __shfl_xor_sync(0xffffffffu, rs0, 1);
        rs0 += __shfl_xor_sync(0xffffffffu, rs0, 2);
        rs1 += __shfl_xor_sync(0xffffffffu, rs1, 1);
        rs1 += __shfl_xor_sync(0xffffffffu, rs1, 2);
        lrow0 = lrow0 * alpha0 + rs0;
        lrow1 = lrow1 * alpha1 + rs1;

        #pragma unroll
        for (int hf = 0; hf < 8; hf++) {
            o[hf][0] *= alpha0; o[hf][1] *= alpha0;
            o[hf][2] *= alpha1; o[hf][3] *= alpha1;
        }

        #pragma unroll
        for (int nf = 0; nf < 8; nf++) {
            uint2 p0 = { f2tf(s[nf][0]), f2tf(s[nf][1]) };
            uint2 p1 = { f2tf(s[nf][2]), f2tf(s[nf][3]) };
            *(uint2*)&Ps[pr0][nf*8 + t4*2] = p0;
            *(uint2*)&Ps[pr1][nf*8 + t4*2] = p1;
        }
        __syncwarp();

        #pragma unroll
        for (int ks = 0; ks < 8; ks++) {
            unsigned pa[4] = { Ps[pr0][ks*8 + t4], Ps[pr1][ks*8 + t4],
                               Ps[pr0][ks*8 + t4 + 4], Ps[pr1][ks*8 + t4 + 4] };
            #pragma unroll
            for (int hf = 0; hf < 8; hf++) {
                unsigned vb[2] = { Vs[ks*8 + t4][hf*8 + g], Vs[ks*8 + t4 + 4][hf*8 + g] };
                mma_tf32(o[hf], pa, vb);
            }
        }
        __syncthreads();
    }

    float inv0 = 1.f / lrow0, inv1 = 1.f / lrow1;
    #pragma unroll
    for (int hf = 0; hf < 8; hf++) {
        int hd = hf*8 + t4*2;
        size_t base0 = ((size_t)b_ * SEQ + qi0) * DMODEL + h_ * HDIM + hd;
        size_t base1 = ((size_t)b_ * SEQ + qi1) * DMODEL + h_ * HDIM + hd;
        float2 w0 = { o[hf][0] * inv0, o[hf][1] * inv0 };
        float2 w1 = { o[hf][2] * inv1, o[hf][3] * inv1 };
        *(float2*)&g_X[base0] = w0;
        *(float2*)&g_X[base1] = w1;
    }
}

// ---------------- launcher -------------------------------------------------
extern "C" void kernel_launch(void* const* d_in, const int* in_sizes, int n_in,
                              void* d_out, int out_size) {
    const float* inputs_q  = (const float*)d_in[0];
    const float* inputs_kv = (const float*)d_in[1];
    const float* Wq = (const float*)d_in[2];
    const float* bq = (const float*)d_in[3];
    const float* Wk = (const float*)d_in[4];
    const float* bk = (const float*)d_in[5];
    const float* Wv = (const float*)d_in[6];
    const float* bv = (const float*)d_in[7];
    const float* Wo = (const float*)d_in[8];
    const float* bo = (const float*)d_in[9];
    const float* rel_bias = (const float*)d_in[10];
    // d_in[11] = pos : unused (index computed analytically in-kernel)
    float* out = (float*)d_out;

    transpose_bias<<<(TABLE * NH + 255) / 256, 256>>>(rel_bias);

    // fused QKV projections: 64 x 36 CTAs
    dim3 gqkv(BATCH * SEQ / 128, 36);
    gemm128<<<gqkv, 256>>>(inputs_q, inputs_kv, Wq, bq, Wk, bk, Wv, bv, nullptr, 0);

    dim3 ga(SEQ / 64, BATCH * NH);            // 16 x 96
    attn_kernel<<<ga, 128>>>();

    // output projection: 64 x 12 CTAs
    dim3 gout(BATCH * SEQ / 128, DMODEL / 64);
    gemm128<<<gout, 256>>>(nullptr, nullptr, Wo, bo, nullptr, nullptr, nullptr, nullptr, out, 1);
}

// round 9
// speedup vs baseline: 1.8587x; 1.5500x over previous
#include <cuda_runtime.h>
#include <cuda_fp16.h>
#include <math_constants.h>
#include <cstdint>

#define BATCH 8
#define SEQ   1024
#define DMODEL 768
#define NH    12
#define HDIM  64
#define IMG   32            // sqrt(SEQ)
#define TABLE 3969          // (2*IMG-1)^2

// ---------------- scratch (device globals: no allocation allowed) ----------
__device__ float g_Q[BATCH*NH*SEQ*HDIM];
__device__ float g_K[BATCH*NH*SEQ*HDIM];
__device__ float g_V[BATCH*NH*SEQ*HDIM];
__device__ float g_X[BATCH*SEQ*DMODEL];
__device__ float g_biasT[NH*TABLE];      // rel_bias transposed: [H][TABLE]

// ---------------- helpers --------------------------------------------------
__device__ __forceinline__ unsigned h2u(__half2 h) { return *(unsigned*)&h; }
__device__ __forceinline__ uint2 f4_to_h4(float4 v) {
    uint2 r;
    r.x = h2u(__floats2half2_rn(v.x, v.y));
    r.y = h2u(__floats2half2_rn(v.z, v.w));
    return r;
}

__device__ __forceinline__ void mma_f16(float* d, const unsigned* a, const unsigned* b) {
    asm volatile("mma.sync.aligned.m16n8k16.row.col.f32.f16.f16.f32 "
        "{%0,%1,%2,%3},{%4,%5,%6,%7},{%8,%9},{%0,%1,%2,%3};"
        : "+f"(d[0]), "+f"(d[1]), "+f"(d[2]), "+f"(d[3])
        : "r"(a[0]), "r"(a[1]), "r"(a[2]), "r"(a[3]),
          "r"(b[0]), "r"(b[1]));
}

__device__ __forceinline__ void ldsm_x4(unsigned& r0, unsigned& r1, unsigned& r2, unsigned& r3,
                                        unsigned addr) {
    asm volatile("ldmatrix.sync.aligned.m8n8.x4.shared.b16 {%0,%1,%2,%3}, [%4];"
        : "=r"(r0), "=r"(r1), "=r"(r2), "=r"(r3) : "r"(addr));
}
__device__ __forceinline__ void ldsm_x4_t(unsigned& r0, unsigned& r1, unsigned& r2, unsigned& r3,
                                          unsigned addr) {
    asm volatile("ldmatrix.sync.aligned.m8n8.x4.trans.shared.b16 {%0,%1,%2,%3}, [%4];"
        : "=r"(r0), "=r"(r1), "=r"(r2), "=r"(r3) : "r"(addr));
}

// ---------------- bias transpose: [TABLE,H] -> [H,TABLE] -------------------
__global__ void transpose_bias(const float* __restrict__ rb) {
    int i = blockIdx.x * blockDim.x + threadIdx.x;
    if (i < TABLE * NH) {
        int t = i / NH, h = i % NH;
        g_biasT[h * TABLE + t] = rb[i];
    }
}

// ---------------- FP16 GEMM, 128x64 tile, 256 thr, double-buffered ---------
// mode 0 (QKV): grid.y = 36; y/12 selects Q/K/V. mode 1: A=g_X -> outPlain.
// As rows: 40 halves (20 words, 20*i mod 32 distinct -> ldmatrix conflict-free)
// Bs rows: 72 halves (36 words, 4*i spread  -> ldmatrix conflict-free)
__global__ void __launch_bounds__(256) gemm128(
    const float* __restrict__ Aq, const float* __restrict__ Akv,
    const float* __restrict__ W0, const float* __restrict__ c0,
    const float* __restrict__ W1, const float* __restrict__ c1,
    const float* __restrict__ W2, const float* __restrict__ c2,
    float* __restrict__ outPlain, int mode)
{
    const int N = DMODEL, K = DMODEL;
    __shared__ __half As[2][128][40];
    __shared__ __half Bs[2][32][72];

    const float* A; const float* W; const float* bias;
    float* outH; float scale; int headmajor;
    int ybase;
    if (mode == 0) {
        int sel = blockIdx.y / 12; ybase = blockIdx.y % 12;
        A    = (sel == 0) ? Aq : Akv;
        W    = (sel == 0) ? W0 : (sel == 1) ? W1 : W2;
        bias = (sel == 0) ? c0 : (sel == 1) ? c1 : c2;
        outH = (sel == 0) ? g_Q : (sel == 1) ? g_K : g_V;
        scale = (sel == 0) ? 0.125f : 1.0f;
        headmajor = 1;
    } else {
        ybase = blockIdx.y;
        A = (const float*)g_X; W = W0; bias = c0;
        outH = outPlain; scale = 1.0f; headmajor = 0;
    }

    int m0 = blockIdx.x * 128, n0 = ybase * 64;
    int tid  = threadIdx.x;
    int lane = tid & 31, warp = tid >> 5;
    int g = lane >> 2, t4 = lane & 3;
    int wm = (warp >> 1) * 32, wn = (warp & 1) * 32;

    unsigned sA = (unsigned)__cvta_generic_to_shared(&As[0][0][0]);
    unsigned sB = (unsigned)__cvta_generic_to_shared(&Bs[0][0][0]);

    // ldmatrix lane-address components (constant per thread)
    int aRowL = (lane & 7) + ((lane & 8) ? 8 : 0);      // + wm + mf*16
    int aColL = (lane & 16) ? 8 : 0;                     // + ks*16
    int bRowL = (lane & 7) + ((lane & 8) ? 8 : 0);      // + ks*16   (trans)
    int bColL = (lane & 16) ? 8 : 0;                     // + wn + nfp*16

    float acc[2][4][4];
    #pragma unroll
    for (int i = 0; i < 2; i++)
        #pragma unroll
        for (int j = 0; j < 4; j++)
            #pragma unroll
            for (int r = 0; r < 4; r++) acc[i][j][r] = 0.f;

    // staging indices
    int aRow[4], aC[4], bRow[2], bC[2];
    #pragma unroll
    for (int j = 0; j < 4; j++) {
        int idx = tid + j * 256;               // 1024 float4 = 128 rows x 8
        aRow[j] = idx >> 3; aC[j] = (idx & 7) << 2;
    }
    #pragma unroll
    for (int j = 0; j < 2; j++) {
        int idx = tid + j * 256;               // 512 float4 = 32 rows x 16
        bRow[j] = idx >> 4; bC[j] = (idx & 15) << 2;
    }

    float4 ar[4], br[2];
    // chunk 0 load + stage
    #pragma unroll
    for (int j = 0; j < 4; j++)
        ar[j] = *(const float4*)(A + (size_t)(m0 + aRow[j]) * K + aC[j]);
    #pragma unroll
    for (int j = 0; j < 2; j++)
        br[j] = *(const float4*)(W + (size_t)bRow[j] * N + n0 + bC[j]);
    #pragma unroll
    for (int j = 0; j < 4; j++) *(uint2*)&As[0][aRow[j]][aC[j]] = f4_to_h4(ar[j]);
    #pragma unroll
    for (int j = 0; j < 2; j++) *(uint2*)&Bs[0][bRow[j]][bC[j]] = f4_to_h4(br[j]);
    __syncthreads();

    const int NCHUNK = K / 32;                 // 24
    for (int kc = 0; kc < NCHUNK; kc++) {
        int cur = kc & 1;
        if (kc + 1 < NCHUNK) {                 // issue next-chunk loads early
            int k0 = (kc + 1) * 32;
            #pragma unroll
            for (int j = 0; j < 4; j++)
                ar[j] = *(const float4*)(A + (size_t)(m0 + aRow[j]) * K + k0 + aC[j]);
            #pragma unroll
            for (int j = 0; j < 2; j++)
                br[j] = *(const float4*)(W + (size_t)(k0 + bRow[j]) * N + n0 + bC[j]);
        }

        #pragma unroll
        for (int ks = 0; ks < 2; ks++) {
            unsigned a[2][4];
            #pragma unroll
            for (int mf = 0; mf < 2; mf++) {
                unsigned addr = sA + ((cur*128 + wm + mf*16 + aRowL) * 40 + ks*16 + aColL) * 2;
                ldsm_x4(a[mf][0], a[mf][1], a[mf][2], a[mf][3], addr);
            }
            #pragma unroll
            for (int nfp = 0; nfp < 2; nfp++) {
                unsigned b0, b1, b2, b3;
                unsigned addr = sB + ((cur*32 + ks*16 + bRowL) * 72 + wn + nfp*16 + bColL) * 2;
                ldsm_x4_t(b0, b1, b2, b3, addr);
                unsigned bb0[2] = { b0, b1 }, bb1[2] = { b2, b3 };
                #pragma unroll
                for (int mf = 0; mf < 2; mf++) {
                    mma_f16(acc[mf][nfp*2    ], a[mf], bb0);
                    mma_f16(acc[mf][nfp*2 + 1], a[mf], bb1);
                }
            }
        }

        if (kc + 1 < NCHUNK) {                 // stage next chunk into other buffer
            int nxt = cur ^ 1;
            #pragma unroll
            for (int j = 0; j < 4; j++) *(uint2*)&As[nxt][aRow[j]][aC[j]] = f4_to_h4(ar[j]);
            #pragma unroll
            for (int j = 0; j < 2; j++) *(uint2*)&Bs[nxt][bRow[j]][bC[j]] = f4_to_h4(br[j]);
        }
        __syncthreads();
    }

    // epilogue (c-layout: rows g/g+8, cols 2t4,2t4+1)
    #pragma unroll
    for (int mf = 0; mf < 2; mf++) {
        #pragma unroll
        for (int nf = 0; nf < 4; nf++) {
            #pragma unroll
            for (int rr = 0; rr < 2; rr++) {
                int m = m0 + wm + mf*16 + g + (rr ? 8 : 0);
                int n = n0 + wn + nf*8 + t4*2;
                float2 v;
                v.x = (acc[mf][nf][rr*2    ] + bias[n    ]) * scale;
                v.y = (acc[mf][nf][rr*2 + 1] + bias[n + 1]) * scale;
                if (headmajor) {
                    int b_ = m >> 10, s_ = m & 1023, h_ = n >> 6, hd = n & 63;
                    *(float2*)&outH[(((size_t)(b_ * NH + h_)) * SEQ + s_) * HDIM + hd] = v;
                } else {
                    *(float2*)&outH[(size_t)m * N + n] = v;
                }
            }
        }
    }
}

// ---------------- FP16 flash attention, analytic relative-position bias ----
// grid (SEQ/64, BATCH*NH), 128 thr; warp owns 16 q rows. No P restage:
// PV A-frags are repacked score C-frags (half2). K/V tiles: 72-half rows
// (36 words -> ldmatrix conflict-free both trans and non-trans).
__global__ void __launch_bounds__(128) attn_kernel()
{
    __shared__ __half Ks[64][72];
    __shared__ __half Vs[64][72];

    int bh = blockIdx.y;
    int b_ = bh / NH, h_ = bh % NH;
    int q0 = blockIdx.x * 64;
    int tid = threadIdx.x, lane = tid & 31, warp = tid >> 5;
    int g = lane >> 2, t4 = lane & 3;

    const float* Qb = g_Q + (size_t)bh * SEQ * HDIM;
    const float* Kb = g_K + (size_t)bh * SEQ * HDIM;
    const float* Vb = g_V + (size_t)bh * SEQ * HDIM;
    const float* biasHT = g_biasT + (size_t)h_ * TABLE;

    unsigned sK = (unsigned)__cvta_generic_to_shared(&Ks[0][0]);
    unsigned sV = (unsigned)__cvta_generic_to_shared(&Vs[0][0]);

    int qi0 = q0 + warp * 16 + g;
    int qi1 = qi0 + 8;
    int qy0 = qi0 >> 5, qx0 = qi0 & 31;
    int qy1 = qi1 >> 5, qx1 = qi1 & 31;

    // Q a-frags (4 ksteps x 4 regs), packed half2 from gmem
    unsigned qa[4][4];
    #pragma unroll
    for (int ks = 0; ks < 4; ks++) {
        float2 v0 = *(const float2*)(Qb + (size_t)qi0 * HDIM + ks*16 + 2*t4);
        float2 v1 = *(const float2*)(Qb + (size_t)qi1 * HDIM + ks*16 + 2*t4);
        float2 v2 = *(const float2*)(Qb + (size_t)qi0 * HDIM + ks*16 + 2*t4 + 8);
        float2 v3 = *(const float2*)(Qb + (size_t)qi1 * HDIM + ks*16 + 2*t4 + 8);
        qa[ks][0] = h2u(__floats2half2_rn(v0.x, v0.y));
        qa[ks][1] = h2u(__floats2half2_rn(v1.x, v1.y));
        qa[ks][2] = h2u(__floats2half2_rn(v2.x, v2.y));
        qa[ks][3] = h2u(__floats2half2_rn(v3.x, v3.y));
    }

    float o[8][4];
    #pragma unroll
    for (int hf = 0; hf < 8; hf++)
        #pragma unroll
        for (int r = 0; r < 4; r++) o[hf][r] = 0.f;

    float mrow0 = -CUDART_INF_F, mrow1 = -CUDART_INF_F;
    float lrow0 = 0.f, lrow1 = 0.f;

    // ldmatrix lane-address components
    int qkRowL = (lane & 7) + ((lane & 16) ? 8 : 0);   // + nfp*16 (Ks rows = kv)
    int qkColL = (lane & 8) ? 8 : 0;                    // + ks*16  (hd)
    int pvRowL = (lane & 7) + ((lane & 8) ? 8 : 0);    // + ks*16  (Vs rows = kv, trans)
    int pvColL = (lane & 16) ? 8 : 0;                   // + hfp*16 (hd)

    for (int kc = 0; kc < 16; kc++) {
        // stage K,V chunk (64 kv x 64 hd) as half
        #pragma unroll
        for (int j = 0; j < 8; j++) {
            int idx = tid + j * 128;
            int row = idx >> 4, c4 = (idx & 15) << 2;
            float4 kv = *(const float4*)(Kb + (size_t)(kc*64 + row) * HDIM + c4);
            *(uint2*)&Ks[row][c4] = f4_to_h4(kv);
            float4 vv = *(const float4*)(Vb + (size_t)(kc*64 + row) * HDIM + c4);
            *(uint2*)&Vs[row][c4] = f4_to_h4(vv);
        }
        __syncthreads();

        // S = Q @ K^T   (16 x 64)
        float s[8][4];
        #pragma unroll
        for (int nf = 0; nf < 8; nf++)
            #pragma unroll
            for (int r = 0; r < 4; r++) s[nf][r] = 0.f;

        #pragma unroll
        for (int ks = 0; ks < 4; ks++) {
            #pragma unroll
            for (int nfp = 0; nfp < 4; nfp++) {
                unsigned b0, b1, b2, b3;
                unsigned addr = sK + ((nfp*16 + qkRowL) * 72 + ks*16 + qkColL) * 2;
                ldsm_x4(b0, b1, b2, b3, addr);
                unsigned bb0[2] = { b0, b1 }, bb1[2] = { b2, b3 };
                mma_f16(s[nfp*2    ], qa[ks], bb0);
                mma_f16(s[nfp*2 + 1], qa[ks], bb1);
            }
        }

        // analytic relative-position bias + online softmax (fp32)
        float mn0 = mrow0, mn1 = mrow1;
        #pragma unroll
        for (int nf = 0; nf < 8; nf++) {
            int colbase = kc*64 + nf*8 + t4*2;
            #pragma unroll
            for (int r = 0; r < 4; r++) {
                int col = colbase + (r & 1);
                int ky = col >> 5, kx = col & 31;
                int qy = (r < 2) ? qy0 : qy1;
                int qx = (r < 2) ? qx0 : qx1;
                int ridx = (qy - ky + (IMG - 1)) * (2*IMG - 1) + (qx - kx + (IMG - 1));
                s[nf][r] += __ldg(biasHT + ridx);
                if (r < 2) mn0 = fmaxf(mn0, s[nf][r]); else mn1 = fmaxf(mn1, s[nf][r]);
            }
        }
        mn0 = fmaxf(mn0, __shfl_xor_sync(0xffffffffu, mn0, 1));
        mn0 = fmaxf(mn0, __shfl_xor_sync(0xffffffffu, mn0, 2));
        mn1 = fmaxf(mn1, __shfl_xor_sync(0xffffffffu, mn1, 1));
        mn1 = fmaxf(mn1, __shfl_xor_sync(0xffffffffu, mn1, 2));

        float alpha0 = __expf(mrow0 - mn0);
        float alpha1 = __expf(mrow1 - mn1);
        mrow0 = mn0; mrow1 = mn1;

        float rs0 = 0.f, rs1 = 0.f;
        #pragma unroll
        for (int nf = 0; nf < 8; nf++) {
            #pragma unroll
            for (int r = 0; r < 4; r++) {
                float p = __expf(s[nf][r] - ((r < 2) ? mn0 : mn1));
                s[nf][r] = p;
                if (r < 2) rs0 += p; else rs1 += p;
            }
        }
        rs0 += __shfl_xor_sync(0xffffffffu, rs0, 1);
        rs0 += __shfl_xor_sync(0xffffffffu, rs0, 2);
        rs1 += __shfl_xor_sync(0xffffffffu, rs1, 1);
        rs1 += __shfl_xor_sync(0xffffffffu, rs1, 2);
        lrow0 = lrow0 * alpha0 + rs0;
        lrow1 = lrow1 * alpha1 + rs1;

        #pragma unroll
        for (int hf = 0; hf < 8; hf++) {
            o[hf][0] *= alpha0; o[hf][1] *= alpha0;
            o[hf][2] *= alpha1; o[hf][3] *= alpha1;
        }

        // O += P @ V ; A-frags = repacked score c-frags (no smem restage)
        #pragma unroll
        for (int ks = 0; ks < 4; ks++) {
            unsigned ap[4];
            ap[0] = h2u(__floats2half2_rn(s[2*ks  ][0], s[2*ks  ][1]));
            ap[1] = h2u(__floats2half2_rn(s[2*ks  ][2], s[2*ks  ][3]));
            ap[2] = h2u(__floats2half2_rn(s[2*ks+1][0], s[2*ks+1][1]));
            ap[3] = h2u(__floats2half2_rn(s[2*ks+1][2], s[2*ks+1][3]));
            #pragma unroll
            for (int hfp = 0; hfp < 4; hfp++) {
                unsigned v0, v1, v2, v3;
                unsigned addr = sV + ((ks*16 + pvRowL) * 72 + hfp*16 + pvColL) * 2;
                ldsm_x4_t(v0, v1, v2, v3, addr);
                unsigned vv0[2] = { v0, v1 }, vv1[2] = { v2, v3 };
                mma_f16(o[hfp*2    ], ap, vv0);
                mma_f16(o[hfp*2 + 1], ap, vv1);
            }
        }
        __syncthreads();
    }

    float inv0 = 1.f / lrow0, inv1 = 1.f / lrow1;
    #pragma unroll
    for (int hf = 0; hf < 8; hf++) {
        int hd = hf*8 + t4*2;
        size_t base0 = ((size_t)b_ * SEQ + qi0) * DMODEL + h_ * HDIM + hd;
        size_t base1 = ((size_t)b_ * SEQ + qi1) * DMODEL + h_ * HDIM + hd;
        float2 w0 = { o[hf][0] * inv0, o[hf][1] * inv0 };
        float2 w1 = { o[hf][2] * inv1, o[hf][3] * inv1 };
        *(float2*)&g_X[base0] = w0;
        *(float2*)&g_X[base1] = w1;
    }
}

// ---------------- launcher -------------------------------------------------
extern "C" void kernel_launch(void* const* d_in, const int* in_sizes, int n_in,
                              void* d_out, int out_size) {
    const float* inputs_q  = (const float*)d_in[0];
    const float* inputs_kv = (const float*)d_in[1];
    const float* Wq = (const float*)d_in[2];
    const float* bq = (const float*)d_in[3];
    const float* Wk = (const float*)d_in[4];
    const float* bk = (const float*)d_in[5];
    const float* Wv = (const float*)d_in[6];
    const float* bv = (const float*)d_in[7];
    const float* Wo = (const float*)d_in[8];
    const float* bo = (const float*)d_in[9];
    const float* rel_bias = (const float*)d_in[10];
    // d_in[11] = pos : unused (index computed analytically in-kernel)
    float* out = (float*)d_out;

    transpose_bias<<<(TABLE * NH + 255) / 256, 256>>>(rel_bias);

    dim3 gqkv(BATCH * SEQ / 128, 36);
    gemm128<<<gqkv, 256>>>(inputs_q, inputs_kv, Wq, bq, Wk, bk, Wv, bv, nullptr, 0);

    dim3 ga(SEQ / 64, BATCH * NH);            // 16 x 96
    attn_kernel<<<ga, 128>>>();

    dim3 gout(BATCH * SEQ / 128, DMODEL / 64);
    gemm128<<<gout, 256>>>(nullptr, nullptr, Wo, bo, nullptr, nullptr, nullptr, nullptr, out, 1);
}

// round 11
// speedup vs baseline: 1.9027x; 1.0237x over previous
#include <cuda_runtime.h>
#include <cuda_fp16.h>
#include <math_constants.h>
#include <cstdint>

#define BATCH 8
#define SEQ   1024
#define DMODEL 768
#define NH    12
#define HDIM  64
#define IMG   32            // sqrt(SEQ)
#define TABLE 3969          // (2*IMG-1)^2

// ---------------- scratch (device globals: no allocation allowed) ----------
__device__ float g_Q[BATCH*NH*SEQ*HDIM];
__device__ float g_K[BATCH*NH*SEQ*HDIM];
__device__ float g_V[BATCH*NH*SEQ*HDIM];
__device__ float g_X[BATCH*SEQ*DMODEL];
__device__ float g_biasT[NH*TABLE];      // rel_bias transposed: [H][TABLE]

// ---------------- helpers --------------------------------------------------
__device__ __forceinline__ unsigned h2u(__half2 h) { return *(unsigned*)&h; }
__device__ __forceinline__ uint2 f4_to_h4(float4 v) {
    uint2 r;
    r.x = h2u(__floats2half2_rn(v.x, v.y));
    r.y = h2u(__floats2half2_rn(v.z, v.w));
    return r;
}

__device__ __forceinline__ void mma_f16(float* d, const unsigned* a, const unsigned* b) {
    asm volatile("mma.sync.aligned.m16n8k16.row.col.f32.f16.f16.f32 "
        "{%0,%1,%2,%3},{%4,%5,%6,%7},{%8,%9},{%0,%1,%2,%3};"
        : "+f"(d[0]), "+f"(d[1]), "+f"(d[2]), "+f"(d[3])
        : "r"(a[0]), "r"(a[1]), "r"(a[2]), "r"(a[3]),
          "r"(b[0]), "r"(b[1]));
}

__device__ __forceinline__ void ldsm_x4(unsigned& r0, unsigned& r1, unsigned& r2, unsigned& r3,
                                        unsigned addr) {
    asm volatile("ldmatrix.sync.aligned.m8n8.x4.shared.b16 {%0,%1,%2,%3}, [%4];"
        : "=r"(r0), "=r"(r1), "=r"(r2), "=r"(r3) : "r"(addr));
}
__device__ __forceinline__ void ldsm_x4_t(unsigned& r0, unsigned& r1, unsigned& r2, unsigned& r3,
                                          unsigned addr) {
    asm volatile("ldmatrix.sync.aligned.m8n8.x4.trans.shared.b16 {%0,%1,%2,%3}, [%4];"
        : "=r"(r0), "=r"(r1), "=r"(r2), "=r"(r3) : "r"(addr));
}

// ---------------- bias transpose: [TABLE,H] -> [H,TABLE] -------------------
__global__ void transpose_bias(const float* __restrict__ rb) {
    int i = blockIdx.x * blockDim.x + threadIdx.x;
    if (i < TABLE * NH) {
        int t = i / NH, h = i % NH;
        g_biasT[h * TABLE + t] = rb[i];
    }
}

// ---------------- FP16 GEMM, 128x128 tile, 256 thr, double-buffered --------
// mode 0 (QKV): grid.y = 18; y/6 selects Q/K/V. mode 1: A=g_X -> outPlain (grid.y=6).
// Warp tile 32x64 (wm = (warp>>1)*32, wn = (warp&1)*64).
// As rows: 40 halves (20 words mod 32 spread -> non-trans ldsm conflict-free)
// Bs rows: 136 halves (68 words = 4 mod 32  -> trans ldsm conflict-free)
__global__ void __launch_bounds__(256) gemm128(
    const float* __restrict__ Aq, const float* __restrict__ Akv,
    const float* __restrict__ W0, const float* __restrict__ c0,
    const float* __restrict__ W1, const float* __restrict__ c1,
    const float* __restrict__ W2, const float* __restrict__ c2,
    float* __restrict__ outPlain, int mode)
{
    const int N = DMODEL, K = DMODEL;
    __shared__ __half As[2][128][40];
    __shared__ __half Bs[2][32][136];

    const float* A; const float* W; const float* bias;
    float* outH; float scale; int headmajor;
    int ybase;
    if (mode == 0) {
        int sel = blockIdx.y / 6; ybase = blockIdx.y % 6;
        A    = (sel == 0) ? Aq : Akv;
        W    = (sel == 0) ? W0 : (sel == 1) ? W1 : W2;
        bias = (sel == 0) ? c0 : (sel == 1) ? c1 : c2;
        outH = (sel == 0) ? g_Q : (sel == 1) ? g_K : g_V;
        scale = (sel == 0) ? 0.125f : 1.0f;
        headmajor = 1;
    } else {
        ybase = blockIdx.y;
        A = (const float*)g_X; W = W0; bias = c0;
        outH = outPlain; scale = 1.0f; headmajor = 0;
    }

    int m0 = blockIdx.x * 128, n0 = ybase * 128;
    int tid  = threadIdx.x;
    int lane = tid & 31, warp = tid >> 5;
    int g = lane >> 2, t4 = lane & 3;
    int wm = (warp >> 1) * 32, wn = (warp & 1) * 64;

    unsigned sA = (unsigned)__cvta_generic_to_shared(&As[0][0][0]);
    unsigned sB = (unsigned)__cvta_generic_to_shared(&Bs[0][0][0]);

    // ldmatrix lane-address components (constant per thread)
    int aRowL = (lane & 7) + ((lane & 8) ? 8 : 0);      // + wm + mf*16
    int aColL = (lane & 16) ? 8 : 0;                     // + ks*16
    int bRowL = (lane & 7) + ((lane & 8) ? 8 : 0);      // + ks*16   (trans)
    int bColL = (lane & 16) ? 8 : 0;                     // + wn + nfp*16

    float acc[2][8][4];
    #pragma unroll
    for (int i = 0; i < 2; i++)
        #pragma unroll
        for (int j = 0; j < 8; j++)
            #pragma unroll
            for (int r = 0; r < 4; r++) acc[i][j][r] = 0.f;

    // staging indices: A 128x32 f32 = 1024 float4; B 32x128 f32 = 1024 float4
    int aRow[4], aC[4], bRow[4], bC[4];
    #pragma unroll
    for (int j = 0; j < 4; j++) {
        int idx = tid + j * 256;
        aRow[j] = idx >> 3;  aC[j] = (idx & 7) << 2;      // 128 rows x 8 float4
        bRow[j] = idx >> 5;  bC[j] = (idx & 31) << 2;     // 32 rows x 32 float4
    }

    float4 ar[4], br[4];
    // chunk 0 load + stage
    #pragma unroll
    for (int j = 0; j < 4; j++) {
        ar[j] = *(const float4*)(A + (size_t)(m0 + aRow[j]) * K + aC[j]);
        br[j] = *(const float4*)(W + (size_t)bRow[j] * N + n0 + bC[j]);
    }
    #pragma unroll
    for (int j = 0; j < 4; j++) {
        *(uint2*)&As[0][aRow[j]][aC[j]] = f4_to_h4(ar[j]);
        *(uint2*)&Bs[0][bRow[j]][bC[j]] = f4_to_h4(br[j]);
    }
    __syncthreads();

    const int NCHUNK = K / 32;                 // 24
    for (int kc = 0; kc < NCHUNK; kc++) {
        int cur = kc & 1;
        if (kc + 1 < NCHUNK) {                 // issue next-chunk loads early
            int k0 = (kc + 1) * 32;
            #pragma unroll
            for (int j = 0; j < 4; j++) {
                ar[j] = *(const float4*)(A + (size_t)(m0 + aRow[j]) * K + k0 + aC[j]);
                br[j] = *(const float4*)(W + (size_t)(k0 + bRow[j]) * N + n0 + bC[j]);
            }
        }

        #pragma unroll
        for (int ks = 0; ks < 2; ks++) {
            unsigned a[2][4];
            #pragma unroll
            for (int mf = 0; mf < 2; mf++) {
                unsigned addr = sA + ((cur*128 + wm + mf*16 + aRowL) * 40 + ks*16 + aColL) * 2;
                ldsm_x4(a[mf][0], a[mf][1], a[mf][2], a[mf][3], addr);
            }
            #pragma unroll
            for (int nfp = 0; nfp < 4; nfp++) {
                unsigned b0, b1, b2, b3;
                unsigned addr = sB + ((cur*32 + ks*16 + bRowL) * 136 + wn + nfp*16 + bColL) * 2;
                ldsm_x4_t(b0, b1, b2, b3, addr);
                unsigned bb0[2] = { b0, b1 }, bb1[2] = { b2, b3 };
                #pragma unroll
                for (int mf = 0; mf < 2; mf++) {
                    mma_f16(acc[mf][nfp*2    ], a[mf], bb0);
                    mma_f16(acc[mf][nfp*2 + 1], a[mf], bb1);
                }
            }
        }

        if (kc + 1 < NCHUNK) {                 // stage next chunk into other buffer
            int nxt = cur ^ 1;
            #pragma unroll
            for (int j = 0; j < 4; j++) {
                *(uint2*)&As[nxt][aRow[j]][aC[j]] = f4_to_h4(ar[j]);
                *(uint2*)&Bs[nxt][bRow[j]][bC[j]] = f4_to_h4(br[j]);
            }
        }
        __syncthreads();
    }

    // epilogue (c-layout: rows g/g+8, cols 2t4,2t4+1)
    #pragma unroll
    for (int mf = 0; mf < 2; mf++) {
        #pragma unroll
        for (int nf = 0; nf < 8; nf++) {
            #pragma unroll
            for (int rr = 0; rr < 2; rr++) {
                int m = m0 + wm + mf*16 + g + (rr ? 8 : 0);
                int n = n0 + wn + nf*8 + t4*2;
                float2 v;
                v.x = (acc[mf][nf][rr*2    ] + bias[n    ]) * scale;
                v.y = (acc[mf][nf][rr*2 + 1] + bias[n + 1]) * scale;
                if (headmajor) {
                    int b_ = m >> 10, s_ = m & 1023, h_ = n >> 6, hd = n & 63;
                    *(float2*)&outH[(((size_t)(b_ * NH + h_)) * SEQ + s_) * HDIM + hd] = v;
                } else {
                    *(float2*)&outH[(size_t)m * N + n] = v;
                }
            }
        }
    }
}

// ---------------- FP16 flash attention, analytic relative-position bias ----
// grid (SEQ/128, BATCH*NH), 256 thr; 8 warps x 16 q rows = 128 q rows/CTA.
// K/V staging amortized over 2x q rows vs 64-row version. No P restage:
// PV A-frags are repacked score C-frags. K/V rows: 72 halves (36 words,
// conflict-free for both trans and non-trans ldsm).
__global__ void __launch_bounds__(256) attn_kernel()
{
    __shared__ __half Ks[64][72];
    __shared__ __half Vs[64][72];

    int bh = blockIdx.y;
    int b_ = bh / NH, h_ = bh % NH;
    int q0 = blockIdx.x * 128;
    int tid = threadIdx.x, lane = tid & 31, warp = tid >> 5;
    int g = lane >> 2, t4 = lane & 3;

    const float* Qb = g_Q + (size_t)bh * SEQ * HDIM;
    const float* Kb = g_K + (size_t)bh * SEQ * HDIM;
    const float* Vb = g_V + (size_t)bh * SEQ * HDIM;
    const float* biasHT = g_biasT + (size_t)h_ * TABLE;

    unsigned sK = (unsigned)__cvta_generic_to_shared(&Ks[0][0]);
    unsigned sV = (unsigned)__cvta_generic_to_shared(&Vs[0][0]);

    int qi0 = q0 + warp * 16 + g;
    int qi1 = qi0 + 8;
    int qy0 = qi0 >> 5, qx0 = qi0 & 31;
    int qy1 = qi1 >> 5, qx1 = qi1 & 31;

    // Q a-frags (4 ksteps x 4 regs), packed half2 from gmem
    unsigned qa[4][4];
    #pragma unroll
    for (int ks = 0; ks < 4; ks++) {
        float2 v0 = *(const float2*)(Qb + (size_t)qi0 * HDIM + ks*16 + 2*t4);
        float2 v1 = *(const float2*)(Qb + (size_t)qi1 * HDIM + ks*16 + 2*t4);
        float2 v2 = *(const float2*)(Qb + (size_t)qi0 * HDIM + ks*16 + 2*t4 + 8);
        float2 v3 = *(const float2*)(Qb + (size_t)qi1 * HDIM + ks*16 + 2*t4 + 8);
        qa[ks][0] = h2u(__floats2half2_rn(v0.x, v0.y));
        qa[ks][1] = h2u(__floats2half2_rn(v1.x, v1.y));
        qa[ks][2] = h2u(__floats2half2_rn(v2.x, v2.y));
        qa[ks][3] = h2u(__floats2half2_rn(v3.x, v3.y));
    }

    float o[8][4];
    #pragma unroll
    for (int hf = 0; hf < 8; hf++)
        #pragma unroll
        for (int r = 0; r < 4; r++) o[hf][r] = 0.f;

    float mrow0 = -CUDART_INF_F, mrow1 = -CUDART_INF_F;
    float lrow0 = 0.f, lrow1 = 0.f;

    // ldmatrix lane-address components
    int qkRowL = (lane & 7) + ((lane & 16) ? 8 : 0);   // + nfp*16 (Ks rows = kv)
    int qkColL = (lane & 8) ? 8 : 0;                    // + ks*16  (hd)
    int pvRowL = (lane & 7) + ((lane & 8) ? 8 : 0);    // + ks*16  (Vs rows = kv, trans)
    int pvColL = (lane & 16) ? 8 : 0;                   // + hfp*16 (hd)

    for (int kc = 0; kc < 16; kc++) {
        // stage K,V chunk (64 kv x 64 hd) as half; 256 threads -> 4 iters
        #pragma unroll
        for (int j = 0; j < 4; j++) {
            int idx = tid + j * 256;
            int row = idx >> 4, c4 = (idx & 15) << 2;
            float4 kv = *(const float4*)(Kb + (size_t)(kc*64 + row) * HDIM + c4);
            *(uint2*)&Ks[row][c4] = f4_to_h4(kv);
            float4 vv = *(const float4*)(Vb + (size_t)(kc*64 + row) * HDIM + c4);
            *(uint2*)&Vs[row][c4] = f4_to_h4(vv);
        }
        __syncthreads();

        // S = Q @ K^T   (16 x 64 per warp)
        float s[8][4];
        #pragma unroll
        for (int nf = 0; nf < 8; nf++)
            #pragma unroll
            for (int r = 0; r < 4; r++) s[nf][r] = 0.f;

        #pragma unroll
        for (int ks = 0; ks < 4; ks++) {
            #pragma unroll
            for (int nfp = 0; nfp < 4; nfp++) {
                unsigned b0, b1, b2, b3;
                unsigned addr = sK + ((nfp*16 + qkRowL) * 72 + ks*16 + qkColL) * 2;
                ldsm_x4(b0, b1, b2, b3, addr);
                unsigned bb0[2] = { b0, b1 }, bb1[2] = { b2, b3 };
                mma_f16(s[nfp*2    ], qa[ks], bb0);
                mma_f16(s[nfp*2 + 1], qa[ks], bb1);
            }
        }

        // analytic relative-position bias + online softmax (fp32)
        float mn0 = mrow0, mn1 = mrow1;
        #pragma unroll
        for (int nf = 0; nf < 8; nf++) {
            int colbase = kc*64 + nf*8 + t4*2;
            #pragma unroll
            for (int r = 0; r < 4; r++) {
                int col = colbase + (r & 1);
                int ky = col >> 5, kx = col & 31;
                int qy = (r < 2) ? qy0 : qy1;
                int qx = (r < 2) ? qx0 : qx1;
                int ridx = (qy - ky + (IMG - 1)) * (2*IMG - 1) + (qx - kx + (IMG - 1));
                s[nf][r] += __ldg(biasHT + ridx);
                if (r < 2) mn0 = fmaxf(mn0, s[nf][r]); else mn1 = fmaxf(mn1, s[nf][r]);
            }
        }
        mn0 = fmaxf(mn0, __shfl_xor_sync(0xffffffffu, mn0, 1));
        mn0 = fmaxf(mn0, __shfl_xor_sync(0xffffffffu, mn0, 2));
        mn1 = fmaxf(mn1, __shfl_xor_sync(0xffffffffu, mn1, 1));
        mn1 = fmaxf(mn1, __shfl_xor_sync(0xffffffffu, mn1, 2));

        float alpha0 = __expf(mrow0 - mn0);
        float alpha1 = __expf(mrow1 - mn1);
        mrow0 = mn0; mrow1 = mn1;

        float rs0 = 0.f, rs1 = 0.f;
        #pragma unroll
        for (int nf = 0; nf < 8; nf++) {
            #pragma unroll
            for (int r = 0; r < 4; r++) {
                float p = __expf(s[nf][r] - ((r < 2) ? mn0 : mn1));
                s[nf][r] = p;
                if (r < 2) rs0 += p; else rs1 += p;
            }
        }
        rs0 += __shfl_xor_sync(0xffffffffu, rs0, 1);
        rs0 += __shfl_xor_sync(0xffffffffu, rs0, 2);
        rs1 += __shfl_xor_sync(0xffffffffu, rs1, 1);
        rs1 += __shfl_xor_sync(0xffffffffu, rs1, 2);
        lrow0 = lrow0 * alpha0 + rs0;
        lrow1 = lrow1 * alpha1 + rs1;

        #pragma unroll
        for (int hf = 0; hf < 8; hf++) {
            o[hf][0] *= alpha0; o[hf][1] *= alpha0;
            o[hf][2] *= alpha1; o[hf][3] *= alpha1;
        }

        // O += P @ V ; A-frags = repacked score c-frags (no smem restage)
        #pragma unroll
        for (int ks = 0; ks < 4; ks++) {
            unsigned ap[4];
            ap[0] = h2u(__floats2half2_rn(s[2*ks  ][0], s[2*ks  ][1]));
            ap[1] = h2u(__floats2half2_rn(s[2*ks  ][2], s[2*ks  ][3]));
            ap[2] = h2u(__floats2half2_rn(s[2*ks+1][0], s[2*ks+1][1]));
            ap[3] = h2u(__floats2half2_rn(s[2*ks+1][2], s[2*ks+1][3]));
            #pragma unroll
            for (int hfp = 0; hfp < 4; hfp++) {
                unsigned v0, v1, v2, v3;
                unsigned addr = sV + ((ks*16 + pvRowL) * 72 + hfp*16 + pvColL) * 2;
                ldsm_x4_t(v0, v1, v2, v3, addr);
                unsigned vv0[2] = { v0, v1 }, vv1[2] = { v2, v3 };
                mma_f16(o[hfp*2    ], ap, vv0);
                mma_f16(o[hfp*2 + 1], ap, vv1);
            }
        }
        __syncthreads();
    }

    float inv0 = 1.f / lrow0, inv1 = 1.f / lrow1;
    #pragma unroll
    for (int hf = 0; hf < 8; hf++) {
        int hd = hf*8 + t4*2;
        size_t base0 = ((size_t)b_ * SEQ + qi0) * DMODEL + h_ * HDIM + hd;
        size_t base1 = ((size_t)b_ * SEQ + qi1) * DMODEL + h_ * HDIM + hd;
        float2 w0 = { o[hf][0] * inv0, o[hf][1] * inv0 };
        float2 w1 = { o[hf][2] * inv1, o[hf][3] * inv1 };
        *(float2*)&g_X[base0] = w0;
        *(float2*)&g_X[base1] = w1;
    }
}

// ---------------- launcher -------------------------------------------------
extern "C" void kernel_launch(void* const* d_in, const int* in_sizes, int n_in,
                              void* d_out, int out_size) {
    const float* inputs_q  = (const float*)d_in[0];
    const float* inputs_kv = (const float*)d_in[1];
    const float* Wq = (const float*)d_in[2];
    const float* bq = (const float*)d_in[3];
    const float* Wk = (const float*)d_in[4];
    const float* bk = (const float*)d_in[5];
    const float* Wv = (const float*)d_in[6];
    const float* bv = (const float*)d_in[7];
    const float* Wo = (const float*)d_in[8];
    const float* bo = (const float*)d_in[9];
    const float* rel_bias = (const float*)d_in[10];
    // d_in[11] = pos : unused (index computed analytically in-kernel)
    float* out = (float*)d_out;

    transpose_bias<<<(TABLE * NH + 255) / 256, 256>>>(rel_bias);

    dim3 gqkv(BATCH * SEQ / 128, 18);         // 64 x 18 (y/6 selects Q/K/V)
    gemm128<<<gqkv, 256>>>(inputs_q, inputs_kv, Wq, bq, Wk, bk, Wv, bv, nullptr, 0);

    dim3 ga(SEQ / 128, BATCH * NH);           // 8 x 96
    attn_kernel<<<ga, 256>>>();

    dim3 gout(BATCH * SEQ / 128, DMODEL / 128);   // 64 x 6
    gemm128<<<gout, 256>>>(nullptr, nullptr, Wo, bo, nullptr, nullptr, nullptr, nullptr, out, 1);
}

// round 14
// speedup vs baseline: 2.3015x; 1.2096x over previous
#include <cuda_runtime.h>
#include <cuda_fp16.h>
#include <math_constants.h>
#include <cstdint>

#define BATCH 8
#define SEQ   1024
#define DMODEL 768
#define NH    12
#define HDIM  64
#define IMG   32            // sqrt(SEQ)
#define TABLE 3969          // (2*IMG-1)^2
#define DD    (DMODEL*DMODEL)

// ---------------- scratch (device globals: no allocation allowed) ----------
__device__ __half g_hAq [BATCH*SEQ*DMODEL];
__device__ __half g_hAkv[BATCH*SEQ*DMODEL];
__device__ __half g_hW  [4*DD];                 // Wq, Wk, Wv, Wo
__device__ __half g_Qh[BATCH*NH*SEQ*HDIM];
__device__ __half g_Kh[BATCH*NH*SEQ*HDIM];
__device__ __half g_Vh[BATCH*NH*SEQ*HDIM];
__device__ __half g_Xh[BATCH*SEQ*DMODEL];
__device__ float  g_biasT[NH*TABLE];            // rel_bias transposed: [H][TABLE]

// ---------------- helpers --------------------------------------------------
__device__ __forceinline__ unsigned h2u(__half2 h) { return *(unsigned*)&h; }
__device__ __forceinline__ uint2 f4_to_h4(float4 v) {
    uint2 r;
    r.x = h2u(__floats2half2_rn(v.x, v.y));
    r.y = h2u(__floats2half2_rn(v.z, v.w));
    return r;
}

__device__ __forceinline__ void mma_f16(float* d, const unsigned* a, const unsigned* b) {
    asm volatile("mma.sync.aligned.m16n8k16.row.col.f32.f16.f16.f32 "
        "{%0,%1,%2,%3},{%4,%5,%6,%7},{%8,%9},{%0,%1,%2,%3};"
        : "+f"(d[0]), "+f"(d[1]), "+f"(d[2]), "+f"(d[3])
        : "r"(a[0]), "r"(a[1]), "r"(a[2]), "r"(a[3]),
          "r"(b[0]), "r"(b[1]));
}

__device__ __forceinline__ void ldsm_x4(unsigned& r0, unsigned& r1, unsigned& r2, unsigned& r3,
                                        unsigned addr) {
    asm volatile("ldmatrix.sync.aligned.m8n8.x4.shared.b16 {%0,%1,%2,%3}, [%4];"
        : "=r"(r0), "=r"(r1), "=r"(r2), "=r"(r3) : "r"(addr));
}
__device__ __forceinline__ void ldsm_x4_t(unsigned& r0, unsigned& r1, unsigned& r2, unsigned& r3,
                                          unsigned addr) {
    asm volatile("ldmatrix.sync.aligned.m8n8.x4.trans.shared.b16 {%0,%1,%2,%3}, [%4];"
        : "=r"(r0), "=r"(r1), "=r"(r2), "=r"(r3) : "r"(addr));
}

__device__ __forceinline__ void cp16(unsigned dst, const void* src) {
    asm volatile("cp.async.cg.shared.global [%0], [%1], 16;" :: "r"(dst), "l"(src) : "memory");
}
#define CP_COMMIT() asm volatile("cp.async.commit_group;" ::: "memory")
#define CP_WAIT0()  asm volatile("cp.async.wait_group 0;" ::: "memory")

// ---------------- conversion kernels ---------------------------------------
__global__ void transpose_bias(const float* __restrict__ rb) {
    int i = blockIdx.x * blockDim.x + threadIdx.x;
    if (i < TABLE * NH) {
        int t = i / NH, h = i % NH;
        g_biasT[h * TABLE + t] = rb[i];
    }
}

__global__ void f2h_inputs(const float* __restrict__ s0, const float* __restrict__ s1, int n4) {
    int i = blockIdx.x * blockDim.x + threadIdx.x;
    const float* s = blockIdx.y ? s1 : s0;
    __half* d = blockIdx.y ? g_hAkv : g_hAq;
    if (i < n4) *((uint2*)d + i) = f4_to_h4(*((const float4*)s + i));
}

__global__ void f2h_weights(const float* __restrict__ s0, const float* __restrict__ s1,
                            const float* __restrict__ s2, const float* __restrict__ s3) {
    int i = blockIdx.x * blockDim.x + threadIdx.x;
    const float* s = (blockIdx.y == 0) ? s0 : (blockIdx.y == 1) ? s1 : (blockIdx.y == 2) ? s2 : s3;
    __half* d = g_hW + (size_t)blockIdx.y * DD;
    const int n4 = DD / 4;
    if (i < n4) *((uint2*)d + i) = f4_to_h4(*((const float4*)s + i));
}

// ---------------- FP16 GEMM, 128x128 tile, 256 thr, cp.async double-buffer -
// mode 0 (QKV): grid.y = 18; y/6 selects Q/K/V (writes half head-major).
// mode 1 (out): grid.y = 6; A = g_Xh, writes f32 outPlain.
// As rows: 40 halves; Bs rows: 136 halves (both ldsm conflict-free; 16B-mult strides)
__global__ void __launch_bounds__(256) gemm128(
    const float* __restrict__ c0, const float* __restrict__ c1, const float* __restrict__ c2,
    float* __restrict__ outPlain, int mode)
{
    const int N = DMODEL, K = DMODEL;
    __shared__ __align__(16) __half As[2][128][40];
    __shared__ __align__(16) __half Bs[2][32][136];

    const __half* A; const __half* W; const float* bias;
    __half* outH; float scale; int ybase;
    if (mode == 0) {
        int sel = blockIdx.y / 6; ybase = blockIdx.y % 6;
        A    = (sel == 0) ? g_hAq : g_hAkv;
        W    = g_hW + (size_t)sel * DD;
        bias = (sel == 0) ? c0 : (sel == 1) ? c1 : c2;
        outH = (sel == 0) ? g_Qh : (sel == 1) ? g_Kh : g_Vh;
        scale = (sel == 0) ? 0.125f : 1.0f;
    } else {
        ybase = blockIdx.y;
        A = g_Xh; W = g_hW + (size_t)3 * DD; bias = c0;
        outH = nullptr; scale = 1.0f;
    }

    int m0 = blockIdx.x * 128, n0 = ybase * 128;
    int tid  = threadIdx.x;
    int lane = tid & 31, warp = tid >> 5;
    int g = lane >> 2, t4 = lane & 3;
    int wm = (warp >> 1) * 32, wn = (warp & 1) * 64;

    unsigned sA = (unsigned)__cvta_generic_to_shared(&As[0][0][0]);
    unsigned sB = (unsigned)__cvta_generic_to_shared(&Bs[0][0][0]);

    int aRowL = (lane & 7) + ((lane & 8) ? 8 : 0);
    int aColL = (lane & 16) ? 8 : 0;
    int bRowL = (lane & 7) + ((lane & 8) ? 8 : 0);
    int bColL = (lane & 16) ? 8 : 0;

    float acc[2][8][4];
    #pragma unroll
    for (int i = 0; i < 2; i++)
        #pragma unroll
        for (int j = 0; j < 8; j++)
            #pragma unroll
            for (int r = 0; r < 4; r++) acc[i][j][r] = 0.f;

    // cp.async staging: A chunk 128x32 halves = 512 x16B; B chunk 32x128 = 512 x16B
    int aSRow[2], aSCol[2], bSRow[2], bSCol[2];
    #pragma unroll
    for (int j = 0; j < 2; j++) {
        int idx = tid + j * 256;
        aSRow[j] = idx >> 2;  aSCol[j] = (idx & 3) * 8;     // 128 rows x 4 chunks
        bSRow[j] = idx >> 4;  bSCol[j] = (idx & 15) * 8;    // 32 rows x 16 chunks
    }

    auto stage = [&](int buf, int k0) {
        #pragma unroll
        for (int j = 0; j < 2; j++)
            cp16(sA + ((buf*128 + aSRow[j]) * 40 + aSCol[j]) * 2,
                 A + (size_t)(m0 + aSRow[j]) * K + k0 + aSCol[j]);
        #pragma unroll
        for (int j = 0; j < 2; j++)
            cp16(sB + ((buf*32 + bSRow[j]) * 136 + bSCol[j]) * 2,
                 W + (size_t)(k0 + bSRow[j]) * N + n0 + bSCol[j]);
        CP_COMMIT();
    };

    stage(0, 0);

    const int NCHUNK = K / 32;                 // 24
    for (int kc = 0; kc < NCHUNK; kc++) {
        int cur = kc & 1;
        CP_WAIT0();
        __syncthreads();
        if (kc + 1 < NCHUNK) stage(cur ^ 1, (kc + 1) * 32);

        #pragma unroll
        for (int ks = 0; ks < 2; ks++) {
            unsigned a[2][4];
            #pragma unroll
            for (int mf = 0; mf < 2; mf++) {
                unsigned addr = sA + ((cur*128 + wm + mf*16 + aRowL) * 40 + ks*16 + aColL) * 2;
                ldsm_x4(a[mf][0], a[mf][1], a[mf][2], a[mf][3], addr);
            }
            #pragma unroll
            for (int nfp = 0; nfp < 4; nfp++) {
                unsigned b0, b1, b2, b3;
                unsigned addr = sB + ((cur*32 + ks*16 + bRowL) * 136 + wn + nfp*16 + bColL) * 2;
                ldsm_x4_t(b0, b1, b2, b3, addr);
                unsigned bb0[2] = { b0, b1 }, bb1[2] = { b2, b3 };
                #pragma unroll
                for (int mf = 0; mf < 2; mf++) {
                    mma_f16(acc[mf][nfp*2    ], a[mf], bb0);
                    mma_f16(acc[mf][nfp*2 + 1], a[mf], bb1);
                }
            }
        }
    }

    // epilogue (c-layout: rows g/g+8, cols 2t4,2t4+1)
    #pragma unroll
    for (int mf = 0; mf < 2; mf++) {
        #pragma unroll
        for (int nf = 0; nf < 8; nf++) {
            #pragma unroll
            for (int rr = 0; rr < 2; rr++) {
                int m = m0 + wm + mf*16 + g + (rr ? 8 : 0);
                int n = n0 + wn + nf*8 + t4*2;
                float vx = (acc[mf][nf][rr*2    ] + bias[n    ]) * scale;
                float vy = (acc[mf][nf][rr*2 + 1] + bias[n + 1]) * scale;
                if (mode == 0) {
                    int b_ = m >> 10, s_ = m & 1023, h_ = n >> 6, hd = n & 63;
                    *(unsigned*)&outH[(((size_t)(b_ * NH + h_)) * SEQ + s_) * HDIM + hd] =
                        h2u(__floats2half2_rn(vx, vy));
                } else {
                    float2 v = { vx, vy };
                    *(float2*)&outPlain[(size_t)m * N + n] = v;
                }
            }
        }
    }
}

// ---------------- FP16 flash attention, cp.async K/V double-buffer ---------
// grid (SEQ/128, BATCH*NH), 256 thr; 8 warps x 16 q rows. No P restage.
// K/V rows: 72 halves (36 words; conflict-free for trans + non-trans ldsm).
__global__ void __launch_bounds__(256) attn_kernel()
{
    __shared__ __align__(16) __half Ks[2][64][72];
    __shared__ __align__(16) __half Vs[2][64][72];

    int bh = blockIdx.y;
    int b_ = bh / NH, h_ = bh % NH;
    int q0 = blockIdx.x * 128;
    int tid = threadIdx.x, lane = tid & 31, warp = tid >> 5;
    int g = lane >> 2, t4 = lane & 3;

    const __half* Qb = g_Qh + (size_t)bh * SEQ * HDIM;
    const __half* Kb = g_Kh + (size_t)bh * SEQ * HDIM;
    const __half* Vb = g_Vh + (size_t)bh * SEQ * HDIM;
    const float* biasHT = g_biasT + (size_t)h_ * TABLE;

    unsigned sK = (unsigned)__cvta_generic_to_shared(&Ks[0][0][0]);
    unsigned sV = (unsigned)__cvta_generic_to_shared(&Vs[0][0][0]);

    int qi0 = q0 + warp * 16 + g;
    int qi1 = qi0 + 8;
    int qy0 = qi0 >> 5, qx0 = qi0 & 31;
    int qy1 = qi1 >> 5, qx1 = qi1 & 31;

    // Q a-frags (4 ksteps x 4 regs), half2 loads from gmem
    unsigned qa[4][4];
    #pragma unroll
    for (int ks = 0; ks < 4; ks++) {
        qa[ks][0] = *(const unsigned*)(Qb + (size_t)qi0 * HDIM + ks*16 + 2*t4);
        qa[ks][1] = *(const unsigned*)(Qb + (size_t)qi1 * HDIM + ks*16 + 2*t4);
        qa[ks][2] = *(const unsigned*)(Qb + (size_t)qi0 * HDIM + ks*16 + 2*t4 + 8);
        qa[ks][3] = *(const unsigned*)(Qb + (size_t)qi1 * HDIM + ks*16 + 2*t4 + 8);
    }

    float o[8][4];
    #pragma unroll
    for (int hf = 0; hf < 8; hf++)
        #pragma unroll
        for (int r = 0; r < 4; r++) o[hf][r] = 0.f;

    float mrow0 = -CUDART_INF_F, mrow1 = -CUDART_INF_F;
    float lrow0 = 0.f, lrow1 = 0.f;

    int qkRowL = (lane & 7) + ((lane & 16) ? 8 : 0);
    int qkColL = (lane & 8) ? 8 : 0;
    int pvRowL = (lane & 7) + ((lane & 8) ? 8 : 0);
    int pvColL = (lane & 16) ? 8 : 0;

    // staging: K/V chunk 64x64 halves = 512 x16B each
    int kvRow[2], kvCol[2];
    #pragma unroll
    for (int j = 0; j < 2; j++) {
        int idx = tid + j * 256;
        kvRow[j] = idx >> 3; kvCol[j] = (idx & 7) * 8;
    }

    auto stage = [&](int buf, int kc) {
        #pragma unroll
        for (int j = 0; j < 2; j++) {
            cp16(sK + ((buf*64 + kvRow[j]) * 72 + kvCol[j]) * 2,
                 Kb + (size_t)(kc*64 + kvRow[j]) * HDIM + kvCol[j]);
            cp16(sV + ((buf*64 + kvRow[j]) * 72 + kvCol[j]) * 2,
                 Vb + (size_t)(kc*64 + kvRow[j]) * HDIM + kvCol[j]);
        }
        CP_COMMIT();
    };

    stage(0, 0);

    for (int kc = 0; kc < 16; kc++) {
        int cur = kc & 1;
        CP_WAIT0();
        __syncthreads();
        if (kc + 1 < 16) stage(cur ^ 1, kc + 1);

        // S = Q @ K^T   (16 x 64 per warp)
        float s[8][4];
        #pragma unroll
        for (int nf = 0; nf < 8; nf++)
            #pragma unroll
            for (int r = 0; r < 4; r++) s[nf][r] = 0.f;

        #pragma unroll
        for (int ks = 0; ks < 4; ks++) {
            #pragma unroll
            for (int nfp = 0; nfp < 4; nfp++) {
                unsigned b0, b1, b2, b3;
                unsigned addr = sK + ((cur*64 + nfp*16 + qkRowL) * 72 + ks*16 + qkColL) * 2;
                ldsm_x4(b0, b1, b2, b3, addr);
                unsigned bb0[2] = { b0, b1 }, bb1[2] = { b2, b3 };
                mma_f16(s[nfp*2    ], qa[ks], bb0);
                mma_f16(s[nfp*2 + 1], qa[ks], bb1);
            }
        }

        // analytic relative-position bias + online softmax (fp32)
        float mn0 = mrow0, mn1 = mrow1;
        #pragma unroll
        for (int nf = 0; nf < 8; nf++) {
            int colbase = kc*64 + nf*8 + t4*2;
            #pragma unroll
            for (int r = 0; r < 4; r++) {
                int col = colbase + (r & 1);
                int ky = col >> 5, kx = col & 31;
                int qy = (r < 2) ? qy0 : qy1;
                int qx = (r < 2) ? qx0 : qx1;
                int ridx = (qy - ky + (IMG - 1)) * (2*IMG - 1) + (qx - kx + (IMG - 1));
                s[nf][r] += __ldg(biasHT + ridx);
                if (r < 2) mn0 = fmaxf(mn0, s[nf][r]); else mn1 = fmaxf(mn1, s[nf][r]);
            }
        }
        mn0 = fmaxf(mn0, __shfl_xor_sync(0xffffffffu, mn0, 1));
        mn0 = fmaxf(mn0, __shfl_xor_sync(0xffffffffu, mn0, 2));
        mn1 = fmaxf(mn1, __shfl_xor_sync(0xffffffffu, mn1, 1));
        mn1 = fmaxf(mn1, __shfl_xor_sync(0xffffffffu, mn1, 2));

        float alpha0 = __expf(mrow0 - mn0);
        float alpha1 = __expf(mrow1 - mn1);
        mrow0 = mn0; mrow1 = mn1;

        float rs0 = 0.f, rs1 = 0.f;
        #pragma unroll
        for (int nf = 0; nf < 8; nf++) {
            #pragma unroll
            for (int r = 0; r < 4; r++) {
                float p = __expf(s[nf][r] - ((r < 2) ? mn0 : mn1));
                s[nf][r] = p;
                if (r < 2) rs0 += p; else rs1 += p;
            }
        }
        rs0 += __shfl_xor_sync(0xffffffffu, rs0, 1);
        rs0 += __shfl_xor_sync(0xffffffffu, rs0, 2);
        rs1 += __shfl_xor_sync(0xffffffffu, rs1, 1);
        rs1 += __shfl_xor_sync(0xffffffffu, rs1, 2);
        lrow0 = lrow0 * alpha0 + rs0;
        lrow1 = lrow1 * alpha1 + rs1;

        #pragma unroll
        for (int hf = 0; hf < 8; hf++) {
            o[hf][0] *= alpha0; o[hf][1] *= alpha0;
            o[hf][2] *= alpha1; o[hf][3] *= alpha1;
        }

        // O += P @ V ; A-frags = repacked score c-frags
        #pragma unroll
        for (int ks = 0; ks < 4; ks++) {
            unsigned ap[4];
            ap[0] = h2u(__floats2half2_rn(s[2*ks  ][0], s[2*ks  ][1]));
            ap[1] = h2u(__floats2half2_rn(s[2*ks  ][2], s[2*ks  ][3]));
            ap[2] = h2u(__floats2half2_rn(s[2*ks+1][0], s[2*ks+1][1]));
            ap[3] = h2u(__floats2half2_rn(s[2*ks+1][2], s[2*ks+1][3]));
            #pragma unroll
            for (int hfp = 0; hfp < 4; hfp++) {
                unsigned v0, v1, v2, v3;
                unsigned addr = sV + ((cur*64 + ks*16 + pvRowL) * 72 + hfp*16 + pvColL) * 2;
                ldsm_x4_t(v0, v1, v2, v3, addr);
                unsigned vv0[2] = { v0, v1 }, vv1[2] = { v2, v3 };
                mma_f16(o[hfp*2    ], ap, vv0);
                mma_f16(o[hfp*2 + 1], ap, vv1);
            }
        }
    }

    float inv0 = 1.f / lrow0, inv1 = 1.f / lrow1;
    #pragma unroll
    for (int hf = 0; hf < 8; hf++) {
        int hd = hf*8 + t4*2;
        size_t base0 = ((size_t)b_ * SEQ + qi0) * DMODEL + h_ * HDIM + hd;
        size_t base1 = ((size_t)b_ * SEQ + qi1) * DMODEL + h_ * HDIM + hd;
        *(unsigned*)&g_Xh[base0] = h2u(__floats2half2_rn(o[hf][0] * inv0, o[hf][1] * inv0));
        *(unsigned*)&g_Xh[base1] = h2u(__floats2half2_rn(o[hf][2] * inv1, o[hf][3] * inv1));
    }
}

// ---------------- launcher -------------------------------------------------
extern "C" void kernel_launch(void* const* d_in, const int* in_sizes, int n_in,
                              void* d_out, int out_size) {
    const float* inputs_q  = (const float*)d_in[0];
    const float* inputs_kv = (const float*)d_in[1];
    const float* Wq = (const float*)d_in[2];
    const float* bq = (const float*)d_in[3];
    const float* Wk = (const float*)d_in[4];
    const float* bk = (const float*)d_in[5];
    const float* Wv = (const float*)d_in[6];
    const float* bv = (const float*)d_in[7];
    const float* Wo = (const float*)d_in[8];
    const float* bo = (const float*)d_in[9];
    const float* rel_bias = (const float*)d_in[10];
    // d_in[11] = pos : unused (index computed analytically in-kernel)
    float* out = (float*)d_out;

    transpose_bias<<<(TABLE * NH + 255) / 256, 256>>>(rel_bias);

    const int NIN4 = BATCH * SEQ * DMODEL / 4;     // 1,572,864
    f2h_inputs<<<dim3((NIN4 + 255) / 256, 2), 256>>>(inputs_q, inputs_kv, NIN4);
    f2h_weights<<<dim3((DD / 4 + 255) / 256, 4), 256>>>(Wq, Wk, Wv, Wo);

    dim3 gqkv(BATCH * SEQ / 128, 18);              // 64 x 18 (y/6 selects Q/K/V)
    gemm128<<<gqkv, 256>>>(bq, bk, bv, nullptr, 0);

    dim3 ga(SEQ / 128, BATCH * NH);                // 8 x 96
    attn_kernel<<<ga, 256>>>();

    dim3 gout(BATCH * SEQ / 128, DMODEL / 128);    // 64 x 6
    gemm128<<<gout, 256>>>(bo, nullptr, nullptr, out, 1);
}

// round 15
// speedup vs baseline: 2.3522x; 1.0220x over previous
#include <cuda_runtime.h>
#include <cuda_fp16.h>
#include <math_constants.h>
#include <cstdint>

#define BATCH 8
#define SEQ   1024
#define DMODEL 768
#define NH    12
#define HDIM  64
#define IMG   32            // sqrt(SEQ)
#define TABLE 3969          // (2*IMG-1)^2
#define DD    (DMODEL*DMODEL)

// ---------------- scratch (device globals: no allocation allowed) ----------
__device__ __half g_hAq [BATCH*SEQ*DMODEL];
__device__ __half g_hAkv[BATCH*SEQ*DMODEL];
__device__ __half g_hW  [4*DD];                 // Wq, Wk, Wv, Wo
__device__ __half g_Qh[BATCH*NH*SEQ*HDIM];
__device__ __half g_Kh[BATCH*NH*SEQ*HDIM];
__device__ __half g_Vh[BATCH*NH*SEQ*HDIM];
__device__ __half g_Xh[BATCH*SEQ*DMODEL];
__device__ float  g_biasT[NH*TABLE];            // rel_bias transposed: [H][TABLE]
__device__ __half g_biasH[(size_t)NH*SEQ*SEQ];  // dense bias: [H][Sq][Sk] (25 MB)

// ---------------- helpers --------------------------------------------------
__device__ __forceinline__ unsigned h2u(__half2 h) { return *(unsigned*)&h; }
__device__ __forceinline__ uint2 f4_to_h4(float4 v) {
    uint2 r;
    r.x = h2u(__floats2half2_rn(v.x, v.y));
    r.y = h2u(__floats2half2_rn(v.z, v.w));
    return r;
}

__device__ __forceinline__ void mma_f16(float* d, const unsigned* a, const unsigned* b) {
    asm volatile("mma.sync.aligned.m16n8k16.row.col.f32.f16.f16.f32 "
        "{%0,%1,%2,%3},{%4,%5,%6,%7},{%8,%9},{%0,%1,%2,%3};"
        : "+f"(d[0]), "+f"(d[1]), "+f"(d[2]), "+f"(d[3])
        : "r"(a[0]), "r"(a[1]), "r"(a[2]), "r"(a[3]),
          "r"(b[0]), "r"(b[1]));
}

__device__ __forceinline__ void ldsm_x4(unsigned& r0, unsigned& r1, unsigned& r2, unsigned& r3,
                                        unsigned addr) {
    asm volatile("ldmatrix.sync.aligned.m8n8.x4.shared.b16 {%0,%1,%2,%3}, [%4];"
        : "=r"(r0), "=r"(r1), "=r"(r2), "=r"(r3) : "r"(addr));
}
__device__ __forceinline__ void ldsm_x4_t(unsigned& r0, unsigned& r1, unsigned& r2, unsigned& r3,
                                          unsigned addr) {
    asm volatile("ldmatrix.sync.aligned.m8n8.x4.trans.shared.b16 {%0,%1,%2,%3}, [%4];"
        : "=r"(r0), "=r"(r1), "=r"(r2), "=r"(r3) : "r"(addr));
}

__device__ __forceinline__ void cp16(unsigned dst, const void* src) {
    asm volatile("cp.async.cg.shared.global [%0], [%1], 16;" :: "r"(dst), "l"(src) : "memory");
}
#define CP_COMMIT() asm volatile("cp.async.commit_group;" ::: "memory")
#define CP_WAIT0()  asm volatile("cp.async.wait_group 0;" ::: "memory")

// ---------------- conversion kernels ---------------------------------------
__global__ void transpose_bias(const float* __restrict__ rb) {
    int i = blockIdx.x * blockDim.x + threadIdx.x;
    if (i < TABLE * NH) {
        int t = i / NH, h = i % NH;
        g_biasT[h * TABLE + t] = rb[i];
    }
}

// dense bias expansion: g_biasH[h][q][k] = table[h][(qy-ky+31)*63 + (qx-kx+31)]
// one thread writes a half2 (k, k+1); k even => kx even => k+1 same ky, ridx-1.
__global__ void bias_expand() {
    int idx = blockIdx.x * blockDim.x + threadIdx.x;
    const int NK2 = SEQ / 2;
    if (idx >= NH * SEQ * NK2) return;
    int k2 = idx % NK2;
    int q  = (idx / NK2) % SEQ;
    int h  = idx / (NK2 * SEQ);
    int k  = k2 * 2;
    int qy = q >> 5, qx = q & 31, ky = k >> 5, kx = k & 31;
    int ridx = (qy - ky + (IMG - 1)) * (2 * IMG - 1) + (qx - kx + (IMG - 1));
    float b0 = g_biasT[h * TABLE + ridx];
    float b1 = g_biasT[h * TABLE + ridx - 1];
    *(__half2*)&g_biasH[((size_t)h * SEQ + q) * SEQ + k] = __floats2half2_rn(b0, b1);
}

__global__ void f2h_inputs(const float* __restrict__ s0, const float* __restrict__ s1, int n4) {
    int i = blockIdx.x * blockDim.x + threadIdx.x;
    const float* s = blockIdx.y ? s1 : s0;
    __half* d = blockIdx.y ? g_hAkv : g_hAq;
    if (i < n4) *((uint2*)d + i) = f4_to_h4(*((const float4*)s + i));
}

__global__ void f2h_weights(const float* __restrict__ s0, const float* __restrict__ s1,
                            const float* __restrict__ s2, const float* __restrict__ s3) {
    int i = blockIdx.x * blockDim.x + threadIdx.x;
    const float* s = (blockIdx.y == 0) ? s0 : (blockIdx.y == 1) ? s1 : (blockIdx.y == 2) ? s2 : s3;
    __half* d = g_hW + (size_t)blockIdx.y * DD;
    const int n4 = DD / 4;
    if (i < n4) *((uint2*)d + i) = f4_to_h4(*((const float4*)s + i));
}

// ---------------- FP16 GEMM, 128x128 tile, 256 thr, cp.async double-buffer -
// mode 0 (QKV): grid.y = 18; y/6 selects Q/K/V (writes half head-major).
// mode 1 (out): grid.y = 6; A = g_Xh, writes f32 outPlain.
__global__ void __launch_bounds__(256) gemm128(
    const float* __restrict__ c0, const float* __restrict__ c1, const float* __restrict__ c2,
    float* __restrict__ outPlain, int mode)
{
    const int N = DMODEL, K = DMODEL;
    __shared__ __align__(16) __half As[2][128][40];
    __shared__ __align__(16) __half Bs[2][32][136];

    const __half* A; const __half* W; const float* bias;
    __half* outH; float scale; int ybase;
    if (mode == 0) {
        int sel = blockIdx.y / 6; ybase = blockIdx.y % 6;
        A    = (sel == 0) ? g_hAq : g_hAkv;
        W    = g_hW + (size_t)sel * DD;
        bias = (sel == 0) ? c0 : (sel == 1) ? c1 : c2;
        outH = (sel == 0) ? g_Qh : (sel == 1) ? g_Kh : g_Vh;
        scale = (sel == 0) ? 0.125f : 1.0f;
    } else {
        ybase = blockIdx.y;
        A = g_Xh; W = g_hW + (size_t)3 * DD; bias = c0;
        outH = nullptr; scale = 1.0f;
    }

    int m0 = blockIdx.x * 128, n0 = ybase * 128;
    int tid  = threadIdx.x;
    int lane = tid & 31, warp = tid >> 5;
    int g = lane >> 2, t4 = lane & 3;
    int wm = (warp >> 1) * 32, wn = (warp & 1) * 64;

    unsigned sA = (unsigned)__cvta_generic_to_shared(&As[0][0][0]);
    unsigned sB = (unsigned)__cvta_generic_to_shared(&Bs[0][0][0]);

    int aRowL = (lane & 7) + ((lane & 8) ? 8 : 0);
    int aColL = (lane & 16) ? 8 : 0;
    int bRowL = (lane & 7) + ((lane & 8) ? 8 : 0);
    int bColL = (lane & 16) ? 8 : 0;

    float acc[2][8][4];
    #pragma unroll
    for (int i = 0; i < 2; i++)
        #pragma unroll
        for (int j = 0; j < 8; j++)
            #pragma unroll
            for (int r = 0; r < 4; r++) acc[i][j][r] = 0.f;

    int aSRow[2], aSCol[2], bSRow[2], bSCol[2];
    #pragma unroll
    for (int j = 0; j < 2; j++) {
        int idx = tid + j * 256;
        aSRow[j] = idx >> 2;  aSCol[j] = (idx & 3) * 8;
        bSRow[j] = idx >> 4;  bSCol[j] = (idx & 15) * 8;
    }

    auto stage = [&](int buf, int k0) {
        #pragma unroll
        for (int j = 0; j < 2; j++)
            cp16(sA + ((buf*128 + aSRow[j]) * 40 + aSCol[j]) * 2,
                 A + (size_t)(m0 + aSRow[j]) * K + k0 + aSCol[j]);
        #pragma unroll
        for (int j = 0; j < 2; j++)
            cp16(sB + ((buf*32 + bSRow[j]) * 136 + bSCol[j]) * 2,
                 W + (size_t)(k0 + bSRow[j]) * N + n0 + bSCol[j]);
        CP_COMMIT();
    };

    stage(0, 0);

    const int NCHUNK = K / 32;                 // 24
    for (int kc = 0; kc < NCHUNK; kc++) {
        int cur = kc & 1;
        CP_WAIT0();
        __syncthreads();
        if (kc + 1 < NCHUNK) stage(cur ^ 1, (kc + 1) * 32);

        #pragma unroll
        for (int ks = 0; ks < 2; ks++) {
            unsigned a[2][4];
            #pragma unroll
            for (int mf = 0; mf < 2; mf++) {
                unsigned addr = sA + ((cur*128 + wm + mf*16 + aRowL) * 40 + ks*16 + aColL) * 2;
                ldsm_x4(a[mf][0], a[mf][1], a[mf][2], a[mf][3], addr);
            }
            #pragma unroll
            for (int nfp = 0; nfp < 4; nfp++) {
                unsigned b0, b1, b2, b3;
                unsigned addr = sB + ((cur*32 + ks*16 + bRowL) * 136 + wn + nfp*16 + bColL) * 2;
                ldsm_x4_t(b0, b1, b2, b3, addr);
                unsigned bb0[2] = { b0, b1 }, bb1[2] = { b2, b3 };
                #pragma unroll
                for (int mf = 0; mf < 2; mf++) {
                    mma_f16(acc[mf][nfp*2    ], a[mf], bb0);
                    mma_f16(acc[mf][nfp*2 + 1], a[mf], bb1);
                }
            }
        }
    }

    // epilogue (c-layout: rows g/g+8, cols 2t4,2t4+1)
    #pragma unroll
    for (int mf = 0; mf < 2; mf++) {
        #pragma unroll
        for (int nf = 0; nf < 8; nf++) {
            #pragma unroll
            for (int rr = 0; rr < 2; rr++) {
                int m = m0 + wm + mf*16 + g + (rr ? 8 : 0);
                int n = n0 + wn + nf*8 + t4*2;
                float vx = (acc[mf][nf][rr*2    ] + bias[n    ]) * scale;
                float vy = (acc[mf][nf][rr*2 + 1] + bias[n + 1]) * scale;
                if (mode == 0) {
                    int b_ = m >> 10, s_ = m & 1023, h_ = n >> 6, hd = n & 63;
                    *(unsigned*)&outH[(((size_t)(b_ * NH + h_)) * SEQ + s_) * HDIM + hd] =
                        h2u(__floats2half2_rn(vx, vy));
                } else {
                    float2 v = { vx, vy };
                    *(float2*)&outPlain[(size_t)m * N + n] = v;
                }
            }
        }
    }
}

// ---------------- FP16 flash attention, dense half bias ---------------------
// grid (SEQ/128, BATCH*NH), 256 thr; 8 warps x 16 q rows. cp.async K/V
// double-buffer; bias via aligned half2 loads from g_biasH (L2-resident).
__global__ void __launch_bounds__(256) attn_kernel()
{
    __shared__ __align__(16) __half Ks[2][64][72];
    __shared__ __align__(16) __half Vs[2][64][72];

    int bh = blockIdx.y;
    int b_ = bh / NH, h_ = bh % NH;
    int q0 = blockIdx.x * 128;
    int tid = threadIdx.x, lane = tid & 31, warp = tid >> 5;
    int g = lane >> 2, t4 = lane & 3;

    const __half* Qb = g_Qh + (size_t)bh * SEQ * HDIM;
    const __half* Kb = g_Kh + (size_t)bh * SEQ * HDIM;
    const __half* Vb = g_Vh + (size_t)bh * SEQ * HDIM;

    unsigned sK = (unsigned)__cvta_generic_to_shared(&Ks[0][0][0]);
    unsigned sV = (unsigned)__cvta_generic_to_shared(&Vs[0][0][0]);

    int qi0 = q0 + warp * 16 + g;
    int qi1 = qi0 + 8;

    const __half* bQ0 = g_biasH + ((size_t)h_ * SEQ + qi0) * SEQ + t4 * 2;
    const __half* bQ1 = g_biasH + ((size_t)h_ * SEQ + qi1) * SEQ + t4 * 2;

    // Q a-frags (4 ksteps x 4 regs), half2 loads from gmem
    unsigned qa[4][4];
    #pragma unroll
    for (int ks = 0; ks < 4; ks++) {
        qa[ks][0] = *(const unsigned*)(Qb + (size_t)qi0 * HDIM + ks*16 + 2*t4);
        qa[ks][1] = *(const unsigned*)(Qb + (size_t)qi1 * HDIM + ks*16 + 2*t4);
        qa[ks][2] = *(const unsigned*)(Qb + (size_t)qi0 * HDIM + ks*16 + 2*t4 + 8);
        qa[ks][3] = *(const unsigned*)(Qb + (size_t)qi1 * HDIM + ks*16 + 2*t4 + 8);
    }

    float o[8][4];
    #pragma unroll
    for (int hf = 0; hf < 8; hf++)
        #pragma unroll
        for (int r = 0; r < 4; r++) o[hf][r] = 0.f;

    float mrow0 = -CUDART_INF_F, mrow1 = -CUDART_INF_F;
    float lrow0 = 0.f, lrow1 = 0.f;

    int qkRowL = (lane & 7) + ((lane & 16) ? 8 : 0);
    int qkColL = (lane & 8) ? 8 : 0;
    int pvRowL = (lane & 7) + ((lane & 8) ? 8 : 0);
    int pvColL = (lane & 16) ? 8 : 0;

    int kvRow[2], kvCol[2];
    #pragma unroll
    for (int j = 0; j < 2; j++) {
        int idx = tid + j * 256;
        kvRow[j] = idx >> 3; kvCol[j] = (idx & 7) * 8;
    }

    auto stage = [&](int buf, int kc) {
        #pragma unroll
        for (int j = 0; j < 2; j++) {
            cp16(sK + ((buf*64 + kvRow[j]) * 72 + kvCol[j]) * 2,
                 Kb + (size_t)(kc*64 + kvRow[j]) * HDIM + kvCol[j]);
            cp16(sV + ((buf*64 + kvRow[j]) * 72 + kvCol[j]) * 2,
                 Vb + (size_t)(kc*64 + kvRow[j]) * HDIM + kvCol[j]);
        }
        CP_COMMIT();
    };

    stage(0, 0);

    for (int kc = 0; kc < 16; kc++) {
        int cur = kc & 1;
        CP_WAIT0();
        __syncthreads();
        if (kc + 1 < 16) stage(cur ^ 1, kc + 1);

        // S = Q @ K^T   (16 x 64 per warp)
        float s[8][4];
        #pragma unroll
        for (int nf = 0; nf < 8; nf++)
            #pragma unroll
            for (int r = 0; r < 4; r++) s[nf][r] = 0.f;

        #pragma unroll
        for (int ks = 0; ks < 4; ks++) {
            #pragma unroll
            for (int nfp = 0; nfp < 4; nfp++) {
                unsigned b0, b1, b2, b3;
                unsigned addr = sK + ((cur*64 + nfp*16 + qkRowL) * 72 + ks*16 + qkColL) * 2;
                ldsm_x4(b0, b1, b2, b3, addr);
                unsigned bb0[2] = { b0, b1 }, bb1[2] = { b2, b3 };
                mma_f16(s[nfp*2    ], qa[ks], bb0);
                mma_f16(s[nfp*2 + 1], qa[ks], bb1);
            }
        }

        // dense bias (aligned half2 loads) + online softmax (fp32)
        float mn0 = mrow0, mn1 = mrow1;
        #pragma unroll
        for (int nf = 0; nf < 8; nf++) {
            int off = kc*64 + nf*8;
            float2 b0 = __half22float2(*(const __half2*)(bQ0 + off));
            float2 b1 = __half22float2(*(const __half2*)(bQ1 + off));
            s[nf][0] += b0.x; s[nf][1] += b0.y;
            s[nf][2] += b1.x; s[nf][3] += b1.y;
            mn0 = fmaxf(mn0, fmaxf(s[nf][0], s[nf][1]));
            mn1 = fmaxf(mn1, fmaxf(s[nf][2], s[nf][3]));
        }
        mn0 = fmaxf(mn0, __shfl_xor_sync(0xffffffffu, mn0, 1));
        mn0 = fmaxf(mn0, __shfl_xor_sync(0xffffffffu, mn0, 2));
        mn1 = fmaxf(mn1, __shfl_xor_sync(0xffffffffu, mn1, 1));
        mn1 = fmaxf(mn1, __shfl_xor_sync(0xffffffffu, mn1, 2));

        float alpha0 = __expf(mrow0 - mn0);
        float alpha1 = __expf(mrow1 - mn1);
        mrow0 = mn0; mrow1 = mn1;

        float rs0 = 0.f, rs1 = 0.f;
        #pragma unroll
        for (int nf = 0; nf < 8; nf++) {
            #pragma unroll
            for (int r = 0; r < 4; r++) {
                float p = __expf(s[nf][r] - ((r < 2) ? mn0 : mn1));
                s[nf][r] = p;
                if (r < 2) rs0 += p; else rs1 += p;
            }
        }
        rs0 += __shfl_xor_sync(0xffffffffu, rs0, 1);
        rs0 += __shfl_xor_sync(0xffffffffu, rs0, 2);
        rs1 += __shfl_xor_sync(0xffffffffu, rs1, 1);
        rs1 += __shfl_xor_sync(0xffffffffu, rs1, 2);
        lrow0 = lrow0 * alpha0 + rs0;
        lrow1 = lrow1 * alpha1 + rs1;

        #pragma unroll
        for (int hf = 0; hf < 8; hf++) {
            o[hf][0] *= alpha0; o[hf][1] *= alpha0;
            o[hf][2] *= alpha1; o[hf][3] *= alpha1;
        }

        // O += P @ V ; A-frags = repacked score c-frags
        #pragma unroll
        for (int ks = 0; ks < 4; ks++) {
            unsigned ap[4];
            ap[0] = h2u(__floats2half2_rn(s[2*ks  ][0], s[2*ks  ][1]));
            ap[1] = h2u(__floats2half2_rn(s[2*ks  ][2], s[2*ks  ][3]));
            ap[2] = h2u(__floats2half2_rn(s[2*ks+1][0], s[2*ks+1][1]));
            ap[3] = h2u(__floats2half2_rn(s[2*ks+1][2], s[2*ks+1][3]));
            #pragma unroll
            for (int hfp = 0; hfp < 4; hfp++) {
                unsigned v0, v1, v2, v3;
                unsigned addr = sV + ((cur*64 + ks*16 + pvRowL) * 72 + hfp*16 + pvColL) * 2;
                ldsm_x4_t(v0, v1, v2, v3, addr);
                unsigned vv0[2] = { v0, v1 }, vv1[2] = { v2, v3 };
                mma_f16(o[hfp*2    ], ap, vv0);
                mma_f16(o[hfp*2 + 1], ap, vv1);
            }
        }
    }

    float inv0 = 1.f / lrow0, inv1 = 1.f / lrow1;
    #pragma unroll
    for (int hf = 0; hf < 8; hf++) {
        int hd = hf*8 + t4*2;
        size_t base0 = ((size_t)b_ * SEQ + qi0) * DMODEL + h_ * HDIM + hd;
        size_t base1 = ((size_t)b_ * SEQ + qi1) * DMODEL + h_ * HDIM + hd;
        *(unsigned*)&g_Xh[base0] = h2u(__floats2half2_rn(o[hf][0] * inv0, o[hf][1] * inv0));
        *(unsigned*)&g_Xh[base1] = h2u(__floats2half2_rn(o[hf][2] * inv1, o[hf][3] * inv1));
    }
}

// ---------------- launcher -------------------------------------------------
extern "C" void kernel_launch(void* const* d_in, const int* in_sizes, int n_in,
                              void* d_out, int out_size) {
    const float* inputs_q  = (const float*)d_in[0];
    const float* inputs_kv = (const float*)d_in[1];
    const float* Wq = (const float*)d_in[2];
    const float* bq = (const float*)d_in[3];
    const float* Wk = (const float*)d_in[4];
    const float* bk = (const float*)d_in[5];
    const float* Wv = (const float*)d_in[6];
    const float* bv = (const float*)d_in[7];
    const float* Wo = (const float*)d_in[8];
    const float* bo = (const float*)d_in[9];
    const float* rel_bias = (const float*)d_in[10];
    // d_in[11] = pos : unused (index computed analytically in-kernel)
    float* out = (float*)d_out;

    transpose_bias<<<(TABLE * NH + 255) / 256, 256>>>(rel_bias);
    bias_expand<<<(NH * SEQ * (SEQ / 2) + 255) / 256, 256>>>();

    const int NIN4 = BATCH * SEQ * DMODEL / 4;     // 1,572,864
    f2h_inputs<<<dim3((NIN4 + 255) / 256, 2), 256>>>(inputs_q, inputs_kv, NIN4);
    f2h_weights<<<dim3((DD / 4 + 255) / 256, 4), 256>>>(Wq, Wk, Wv, Wo);

    dim3 gqkv(BATCH * SEQ / 128, 18);              // 64 x 18 (y/6 selects Q/K/V)
    gemm128<<<gqkv, 256>>>(bq, bk, bv, nullptr, 0);

    dim3 ga(SEQ / 128, BATCH * NH);                // 8 x 96
    attn_kernel<<<ga, 256>>>();

    dim3 gout(BATCH * SEQ / 128, DMODEL / 128);    // 64 x 6
    gemm128<<<gout, 256>>>(bo, nullptr, nullptr, out, 1);
}